// round 7
// baseline (speedup 1.0000x reference)
#include <cuda_runtime.h>
#include <cuda_fp16.h>
#include <math_constants.h>
#include <cstdint>

#define C_DIM 128
#define D_DEG 64
#define NODE_NUM 8192
#define N_TOTAL 200000
#define NEG_SLOPE 0.2f
#define NWARPS 16            // 512 threads
#define GRID_CTAS 296        // 2 persistent CTAs per SM

// smem layout (dynamic) for gather kernel
#define OFF_STG   0                        // stage S rows [64][128] fp16 = 16KB
#define OFF_PART  16384                    // part [16][128] f32 = 8KB
#define OFF_SRAW  24576                    // [64] f32
#define OFF_SARR  24832                    // [64] f32
#define OFF_WRED  25088                    // [16] f32
#define SMEM_BYTES 25152

// Fused fp16 table: S[n][c] = fp16(feat[n][c] + mem[n][c]); 51.2MB static scratch.
__device__ __half2 g_S[(size_t)N_TOTAL * (C_DIM / 2)];
// Folded weights: v = W_max @ W_score[:128]; c0 = dot(b_max, W_score[:128]) + b_score
__device__ float g_v[C_DIM];
__device__ float g_c0;

// ---- Kernel 1: streaming fuse (feat+mem -> fp16 S) + weight folding ----
__global__ __launch_bounds__(512)
void fuse_kernel(const float4* __restrict__ feat4,
                 const float4* __restrict__ mem4,
                 const float* __restrict__ Wmax,
                 const float* __restrict__ bmax,
                 const float* __restrict__ Wscore,
                 const float* __restrict__ bscore) {
    if (blockIdx.x == 0) {
        __shared__ float ws1[C_DIM];
        int t = threadIdx.x;
        if (t < C_DIM) ws1[t] = Wscore[t];
        __syncthreads();
        if (t < C_DIM) {
            const float* row = Wmax + t * C_DIM;
            float acc = 0.f;
#pragma unroll 8
            for (int k = 0; k < C_DIM; k++) acc += row[k] * ws1[k];
            g_v[t] = acc;
            if (t == 0) {
                float c0 = bscore[0];
                for (int k = 0; k < C_DIM; k++) c0 += bmax[k] * ws1[k];
                g_c0 = c0;
            }
        }
    }
    const int total = N_TOTAL * (C_DIM / 4);   // 6.4M float4-groups
    const int stride = gridDim.x * blockDim.x;
    for (int i = blockIdx.x * blockDim.x + threadIdx.x; i < total; i += stride) {
        float4 a = feat4[i];
        float4 b = mem4[i];
        __half2 h0 = __floats2half2_rn(a.x + b.x, a.y + b.y);
        __half2 h1 = __floats2half2_rn(a.z + b.z, a.w + b.w);
        uint2 pack;
        pack.x = *reinterpret_cast<unsigned int*>(&h0);
        pack.y = *reinterpret_cast<unsigned int*>(&h1);
        *reinterpret_cast<uint2*>(&g_S[2 * (size_t)i]) = pack;   // 8B store
    }
}

__device__ __forceinline__ void cp8(unsigned int dst, const void* src) {
    asm volatile("cp.async.ca.shared.global [%0], [%1], 8;\n"
                 :: "r"(dst), "l"(src) : "memory");
}

// ---- Kernel 2: gather from fp16 S (L2-resident) + full graph pipeline ----
__global__ __launch_bounds__(512, 2)
void community_kernel(const float* __restrict__ Wscore,
                      const float* __restrict__ Wfit,
                      const float* __restrict__ bfit,
                      float* __restrict__ out_cluster,   // [NODE_NUM, C]
                      float* __restrict__ out_scores,    // [NODE_NUM, D]
                      float* __restrict__ out_fit,       // [NODE_NUM]
                      const int* __restrict__ neighbors)
{
    extern __shared__ char smem[];
    __half2* stg = (__half2*)(smem + OFF_STG);   // [64][64] half2
    float* part  = (float*)(smem + OFF_PART);    // [16][128]
    float* sraw  = (float*)(smem + OFF_SRAW);
    float* sarr  = (float*)(smem + OFF_SARR);
    float* wred  = (float*)(smem + OFF_WRED);

    const unsigned int stg_u = (unsigned int)__cvta_generic_to_shared(stg);
    const char* Sbase = (const char*)g_S;

    const int t    = threadIdx.x;
    const int lane = t & 31;
    const int wid  = t >> 5;   // 0..15

    // loop-invariant weights in registers
    const float4 w2v   = *reinterpret_cast<const float4*>(Wscore + C_DIM + 4 * lane);
    const float  gv    = (t < C_DIM) ? g_v[t]  : 0.f;
    const float  wfitv = (t < C_DIM) ? Wfit[t] : 0.f;
    const float  bfitv = bfit[0];
    const float  c0    = g_c0;

    int node = blockIdx.x;

    // ---- prologue: stage first node's rows (8B per lane per row) ----
    {
#pragma unroll
        for (int i = 0; i < 4; i++) {
            int row = i * NWARPS + wid;
            long long nid = neighbors[node * D_DEG + row];
            cp8(stg_u + (unsigned)(row * 256 + lane * 8),
                Sbase + nid * 256 + lane * 8);
        }
        asm volatile("cp.async.commit_group;\n" ::: "memory");
    }

    while (true) {
        const int  next     = node + GRID_CTAS;
        const bool has_next = (next < NODE_NUM);

        asm volatile("cp.async.wait_group 0;\n" ::: "memory");

        // ---- stage -> registers (own bytes only), fp16 -> f32 ----
        float4 nb[4];
#pragma unroll
        for (int i = 0; i < 4; i++) {
            int row = i * NWARPS + wid;
            uint2 u = *reinterpret_cast<const uint2*>(stg + row * 64 + lane * 2);
            __half2 p0 = *reinterpret_cast<__half2*>(&u.x);
            __half2 p1 = *reinterpret_cast<__half2*>(&u.y);
            float2 f0 = __half22float2(p0);
            float2 f1 = __half22float2(p1);
            nb[i] = make_float4(f0.x, f0.y, f1.x, f1.y);
        }

        // ---- immediately issue next node's stage ----
        if (has_next) {
#pragma unroll
            for (int i = 0; i < 4; i++) {
                int row = i * NWARPS + wid;
                long long nid = neighbors[next * D_DEG + row];
                cp8(stg_u + (unsigned)(row * 256 + lane * 8),
                    Sbase + nid * 256 + lane * 8);
            }
            asm volatile("cp.async.commit_group;\n" ::: "memory");
        }

        // ---- fused column-max + per-row score dot ----
        float4 cmax = make_float4(-CUDART_INF_F, -CUDART_INF_F, -CUDART_INF_F, -CUDART_INF_F);
#pragma unroll
        for (int i = 0; i < 4; i++) {
            cmax.x = fmaxf(cmax.x, nb[i].x);
            cmax.y = fmaxf(cmax.y, nb[i].y);
            cmax.z = fmaxf(cmax.z, nb[i].z);
            cmax.w = fmaxf(cmax.w, nb[i].w);
            float p = nb[i].x * w2v.x + nb[i].y * w2v.y + nb[i].z * w2v.z + nb[i].w * w2v.w;
#pragma unroll
            for (int o = 16; o > 0; o >>= 1) p += __shfl_xor_sync(0xffffffffu, p, o);
            if (lane == 0) sraw[i * NWARPS + wid] = p;
        }
        reinterpret_cast<float4*>(part + wid * C_DIM)[lane] = cmax;
        __syncthreads();  // B1: part + sraw ready

        // ---- s_const = dot(colmax, v) + c0 ----
        if (t < C_DIM) {
            float cm = -CUDART_INF_F;
#pragma unroll
            for (int w = 0; w < NWARPS; w++) cm = fmaxf(cm, part[w * C_DIM + t]);
            float p = cm * gv;
#pragma unroll
            for (int o = 16; o > 0; o >>= 1) p += __shfl_xor_sync(0xffffffffu, p, o);
            if (lane == 0) wred[wid] = p;
        }
        __syncthreads();  // B2

        // ---- warp 0: leaky-relu + segment softmax ----
        if (wid == 0) {
            const float s_const = wred[0] + wred[1] + wred[2] + wred[3] + c0;
            float a0 = s_const + sraw[lane];
            float a1 = s_const + sraw[lane + 32];
            a0 = (a0 >= 0.f) ? a0 : NEG_SLOPE * a0;
            a1 = (a1 >= 0.f) ? a1 : NEG_SLOPE * a1;
            float mx = fmaxf(a0, a1);
#pragma unroll
            for (int o = 16; o > 0; o >>= 1) mx = fmaxf(mx, __shfl_xor_sync(0xffffffffu, mx, o));
            float e0 = __expf(a0 - mx), e1 = __expf(a1 - mx);
            float sm = e0 + e1;
#pragma unroll
            for (int o = 16; o > 0; o >>= 1) sm += __shfl_xor_sync(0xffffffffu, sm, o);
            float inv = 1.f / sm;
            sarr[lane]      = e0 * inv;
            sarr[lane + 32] = e1 * inv;
        }
        __syncthreads();  // B3: sarr ready

        if (t < D_DEG) out_scores[node * D_DEG + t] = sarr[t];

        // ---- weighted pooling from registers ----
        float4 pool = make_float4(0.f, 0.f, 0.f, 0.f);
#pragma unroll
        for (int i = 0; i < 4; i++) {
            float sc = sarr[i * NWARPS + wid];
            pool.x = fmaf(sc, nb[i].x, pool.x);
            pool.y = fmaf(sc, nb[i].y, pool.y);
            pool.z = fmaf(sc, nb[i].z, pool.z);
            pool.w = fmaf(sc, nb[i].w, pool.w);
        }
        reinterpret_cast<float4*>(part + wid * C_DIM)[lane] = pool;
        __syncthreads();  // B4

        // ---- cross-warp sum, write cluster, fused fitness dot ----
        if (t < C_DIM) {
            float cf = 0.f;
#pragma unroll
            for (int w = 0; w < NWARPS; w++) cf += part[w * C_DIM + t];
            out_cluster[node * C_DIM + t] = cf;
            float p = cf * wfitv;
#pragma unroll
            for (int o = 16; o > 0; o >>= 1) p += __shfl_xor_sync(0xffffffffu, p, o);
            if (lane == 0) wred[wid] = p;
        }
        __syncthreads();  // B5

        if (t == 0) {
            float s = wred[0] + wred[1] + wred[2] + wred[3] + bfitv;
            out_fit[node] = 1.f / (1.f + __expf(-s));
        }

        if (!has_next) break;
        node = next;
    }
}

extern "C" void kernel_launch(void* const* d_in, const int* in_sizes, int n_in,
                              void* d_out, int out_size) {
    const float* feat   = (const float*)d_in[0];
    const float* mem    = (const float*)d_in[1];
    const float* Wmax   = (const float*)d_in[2];
    const float* bmax   = (const float*)d_in[3];
    const float* Wscore = (const float*)d_in[4];
    const float* bscore = (const float*)d_in[5];
    const float* Wfit   = (const float*)d_in[6];
    const float* bfit   = (const float*)d_in[7];
    const int*   nbrs   = (const int*)d_in[8];

    float* out = (float*)d_out;
    float* out_cluster = out;                                        // 8192*128
    float* out_scores  = out + NODE_NUM * C_DIM;                     // 8192*64
    float* out_fit     = out + NODE_NUM * C_DIM + NODE_NUM * D_DEG;  // 8192

    cudaFuncSetAttribute(community_kernel,
                         cudaFuncAttributeMaxDynamicSharedMemorySize, SMEM_BYTES);

    fuse_kernel<<<4096, 512>>>((const float4*)feat, (const float4*)mem,
                               Wmax, bmax, Wscore, bscore);
    community_kernel<<<GRID_CTAS, 512, SMEM_BYTES>>>(Wscore, Wfit, bfit,
                                                     out_cluster, out_scores, out_fit, nbrs);
}

// round 8
// speedup vs baseline: 1.2875x; 1.2875x over previous
#include <cuda_runtime.h>
#include <cuda_fp16.h>
#include <math_constants.h>
#include <cstdint>

#define C_DIM 128
#define D_DEG 64
#define NODE_NUM 8192
#define N_TOTAL 200000
#define NEG_SLOPE 0.2f
#define GRID_CTAS 296        // 2 persistent CTAs per SM
#define GROUPS 4             // independent 128-thread groups per CTA
#define GSTREAMS (GRID_CTAS * GROUPS)   // 1184 node streams

// smem layout (dynamic)
#define OFF_STAGE 0                 // [4][64][128] fp16 = 4 x 16KB
#define OFF_PART  65536             // [4][4][128] f32  = 8KB
#define OFF_SRAW  73728             // [4][64] f32
#define OFF_SARR  74752             // [4][64] f32
#define OFF_WRED  75776             // [4][4]  f32
#define SMEM_BYTES 75840

// Fused fp16 table: S[n][c] = fp16(feat[n][c] + mem[n][c]); 51.2MB static scratch.
__device__ __half2 g_S[(size_t)N_TOTAL * (C_DIM / 2)];
// Folded weights: v = W_max @ W_score[:128]; c0 = dot(b_max, W_score[:128]) + b_score
__device__ float g_v[C_DIM];
__device__ float g_c0;

// ---- Kernel 1: streaming fuse (feat+mem -> fp16 S) + weight folding ----
__global__ __launch_bounds__(512)
void fuse_kernel(const float4* __restrict__ feat4,
                 const float4* __restrict__ mem4,
                 const float* __restrict__ Wmax,
                 const float* __restrict__ bmax,
                 const float* __restrict__ Wscore,
                 const float* __restrict__ bscore) {
    if (blockIdx.x == 0) {
        __shared__ float ws1[C_DIM];
        int t = threadIdx.x;
        if (t < C_DIM) ws1[t] = Wscore[t];
        __syncthreads();
        if (t < C_DIM) {
            const float* row = Wmax + t * C_DIM;
            float acc = 0.f;
#pragma unroll 8
            for (int k = 0; k < C_DIM; k++) acc += row[k] * ws1[k];
            g_v[t] = acc;
            if (t == 0) {
                float c0 = bscore[0];
                for (int k = 0; k < C_DIM; k++) c0 += bmax[k] * ws1[k];
                g_c0 = c0;
            }
        }
    }
    const int total = N_TOTAL * (C_DIM / 4);   // 6.4M float4-groups
    const int stride = gridDim.x * blockDim.x;
    for (int i = blockIdx.x * blockDim.x + threadIdx.x; i < total; i += stride) {
        float4 a = feat4[i];
        float4 b = mem4[i];
        __half2 h0 = __floats2half2_rn(a.x + b.x, a.y + b.y);
        __half2 h1 = __floats2half2_rn(a.z + b.z, a.w + b.w);
        uint2 pack;
        pack.x = *reinterpret_cast<unsigned int*>(&h0);
        pack.y = *reinterpret_cast<unsigned int*>(&h1);
        *reinterpret_cast<uint2*>(&g_S[2 * (size_t)i]) = pack;   // 8B store
    }
}

__device__ __forceinline__ void cp16(unsigned int dst, const void* src) {
    asm volatile("cp.async.cg.shared.global [%0], [%1], 16;\n"
                 :: "r"(dst), "l"(src) : "memory");
}
__device__ __forceinline__ void gbar(int id) {
    asm volatile("bar.sync %0, 128;" :: "r"(id) : "memory");
}

// ---- Kernel 2: 4 independent warpgroup node-pipelines per CTA ----
__global__ __launch_bounds__(512, 2)
void community_kernel(const float* __restrict__ Wscore,
                      const float* __restrict__ Wfit,
                      const float* __restrict__ bfit,
                      float* __restrict__ out_cluster,   // [NODE_NUM, C]
                      float* __restrict__ out_scores,    // [NODE_NUM, D]
                      float* __restrict__ out_fit,       // [NODE_NUM]
                      const int* __restrict__ neighbors)
{
    extern __shared__ char smem[];

    const int t    = threadIdx.x;
    const int lane = t & 31;
    const int wid  = t >> 5;     // 0..15
    const int g    = wid >> 2;   // group 0..3
    const int gw   = wid & 3;    // warp within group
    const int tg   = t & 127;    // thread within group
    const int barid = g + 1;

    __half2* stg   = (__half2*)(smem + OFF_STAGE) + g * 4096;   // [64][64] half2
    float*   partg = (float*)(smem + OFF_PART) + g * 512;       // [4][128]
    float*   srawg = (float*)(smem + OFF_SRAW) + g * 64;
    float*   sarrg = (float*)(smem + OFF_SARR) + g * 64;
    float*   wredg = (float*)(smem + OFF_WRED) + g * 4;
    const unsigned int stg_u = (unsigned int)__cvta_generic_to_shared(stg);
    const char* Sbase = (const char*)g_S;

    // loop-invariant weights
    const float4 w2v   = *reinterpret_cast<const float4*>(Wscore + C_DIM + 4 * lane);
    const float  gv    = g_v[tg];
    const float  wfitv = Wfit[tg];
    const float  bfitv = bfit[0];
    const float  c0    = g_c0;

    int node = blockIdx.x * GROUPS + g;

    // ---- prologue: stage first node (each thread: 8 x 16B chunks) ----
#pragma unroll
    for (int i = 0; i < 8; i++) {
        int k = i * 128 + tg;            // 0..1023 chunk id
        int row = k >> 4, ch = k & 15;
        long long nid = neighbors[node * D_DEG + row];
        cp16(stg_u + (unsigned)k * 16u, Sbase + nid * 256 + ch * 16);
    }
    asm volatile("cp.async.commit_group;\n" ::: "memory");

    while (true) {
        const int  next     = node + GSTREAMS;
        const bool has_next = (next < NODE_NUM);

        asm volatile("cp.async.wait_group 0;\n" ::: "memory");
        gbar(barid);   // B1: stage visible to all 128 threads of group

        // ---- Phase A: per-row score dot + column max (warp gw: rows gw*16..+15)
        float cm0 = -CUDART_INF_F, cm1 = -CUDART_INF_F, cm2 = -CUDART_INF_F, cm3 = -CUDART_INF_F;
#pragma unroll
        for (int r = 0; r < 16; r++) {
            int row = gw * 16 + r;
            uint2 u = *reinterpret_cast<const uint2*>(stg + row * 64 + lane * 2);
            __half2 h0 = *reinterpret_cast<__half2*>(&u.x);
            __half2 h1 = *reinterpret_cast<__half2*>(&u.y);
            float2 f0 = __half22float2(h0);
            float2 f1 = __half22float2(h1);
            cm0 = fmaxf(cm0, f0.x); cm1 = fmaxf(cm1, f0.y);
            cm2 = fmaxf(cm2, f1.x); cm3 = fmaxf(cm3, f1.y);
            float p = f0.x * w2v.x + f0.y * w2v.y + f1.x * w2v.z + f1.y * w2v.w;
#pragma unroll
            for (int o = 16; o > 0; o >>= 1) p += __shfl_xor_sync(0xffffffffu, p, o);
            if (lane == 0) srawg[row] = p;
        }
        {
            float4 cmv = make_float4(cm0, cm1, cm2, cm3);
            *reinterpret_cast<float4*>(partg + gw * 128 + lane * 4) = cmv;
        }
        gbar(barid);   // B2: part + sraw ready

        // ---- Phase B: 4-warp colmax + dot with g_v ----
        {
            float cm = fmaxf(fmaxf(partg[tg], partg[128 + tg]),
                             fmaxf(partg[256 + tg], partg[384 + tg]));
            float p = cm * gv;
#pragma unroll
            for (int o = 16; o > 0; o >>= 1) p += __shfl_xor_sync(0xffffffffu, p, o);
            if (lane == 0) wredg[gw] = p;
        }
        gbar(barid);   // B3: wred ready

        // ---- Phase C: warp 0 of group: leaky-relu + softmax + score output ----
        if (gw == 0) {
            const float s_const = wredg[0] + wredg[1] + wredg[2] + wredg[3] + c0;
            float a0 = s_const + srawg[lane];
            float a1 = s_const + srawg[lane + 32];
            a0 = (a0 >= 0.f) ? a0 : NEG_SLOPE * a0;
            a1 = (a1 >= 0.f) ? a1 : NEG_SLOPE * a1;
            float mx = fmaxf(a0, a1);
#pragma unroll
            for (int o = 16; o > 0; o >>= 1) mx = fmaxf(mx, __shfl_xor_sync(0xffffffffu, mx, o));
            float e0 = __expf(a0 - mx), e1 = __expf(a1 - mx);
            float sm = e0 + e1;
#pragma unroll
            for (int o = 16; o > 0; o >>= 1) sm += __shfl_xor_sync(0xffffffffu, sm, o);
            float inv = 1.f / sm;
            float s0 = e0 * inv, s1 = e1 * inv;
            sarrg[lane]      = s0;
            sarrg[lane + 32] = s1;
            out_scores[node * D_DEG + lane]      = s0;
            out_scores[node * D_DEG + lane + 32] = s1;
        }
        gbar(barid);   // B4: sarr ready

        // ---- Phase D: weighted pooling (re-read own rows from stage) ----
        float a0 = 0.f, a1 = 0.f, a2 = 0.f, a3 = 0.f;
#pragma unroll
        for (int r = 0; r < 16; r++) {
            int row = gw * 16 + r;
            float sc = sarrg[row];
            uint2 u = *reinterpret_cast<const uint2*>(stg + row * 64 + lane * 2);
            __half2 h0 = *reinterpret_cast<__half2*>(&u.x);
            __half2 h1 = *reinterpret_cast<__half2*>(&u.y);
            float2 f0 = __half22float2(h0);
            float2 f1 = __half22float2(h1);
            a0 = fmaf(sc, f0.x, a0); a1 = fmaf(sc, f0.y, a1);
            a2 = fmaf(sc, f1.x, a2); a3 = fmaf(sc, f1.y, a3);
        }
        *reinterpret_cast<float4*>(partg + gw * 128 + lane * 4) = make_float4(a0, a1, a2, a3);
        gbar(barid);   // B5: pool partials ready; stage reads complete

        // ---- prefetch next node's stage (stage free now) ----
        if (has_next) {
#pragma unroll
            for (int i = 0; i < 8; i++) {
                int k = i * 128 + tg;
                int row = k >> 4, ch = k & 15;
                long long nid = neighbors[next * D_DEG + row];
                cp16(stg_u + (unsigned)k * 16u, Sbase + nid * 256 + ch * 16);
            }
            asm volatile("cp.async.commit_group;\n" ::: "memory");
        }

        // ---- Phase E: cluster sum + output + fused fitness dot ----
        {
            float cf = partg[tg] + partg[128 + tg] + partg[256 + tg] + partg[384 + tg];
            out_cluster[node * C_DIM + tg] = cf;
            float p = cf * wfitv;
#pragma unroll
            for (int o = 16; o > 0; o >>= 1) p += __shfl_xor_sync(0xffffffffu, p, o);
            if (lane == 0) wredg[gw] = p;
        }
        gbar(barid);   // B6: wred ready
        if (tg == 0) {
            float s = wredg[0] + wredg[1] + wredg[2] + wredg[3] + bfitv;
            out_fit[node] = 1.f / (1.f + __expf(-s));
        }
        // wredg next written in Phase B of next iter (after B1+B2) -> safe.

        if (!has_next) break;
        node = next;
    }
}

extern "C" void kernel_launch(void* const* d_in, const int* in_sizes, int n_in,
                              void* d_out, int out_size) {
    const float* feat   = (const float*)d_in[0];
    const float* mem    = (const float*)d_in[1];
    const float* Wmax   = (const float*)d_in[2];
    const float* bmax   = (const float*)d_in[3];
    const float* Wscore = (const float*)d_in[4];
    const float* bscore = (const float*)d_in[5];
    const float* Wfit   = (const float*)d_in[6];
    const float* bfit   = (const float*)d_in[7];
    const int*   nbrs   = (const int*)d_in[8];

    float* out = (float*)d_out;
    float* out_cluster = out;                                        // 8192*128
    float* out_scores  = out + NODE_NUM * C_DIM;                     // 8192*64
    float* out_fit     = out + NODE_NUM * C_DIM + NODE_NUM * D_DEG;  // 8192

    cudaFuncSetAttribute(community_kernel,
                         cudaFuncAttributeMaxDynamicSharedMemorySize, SMEM_BYTES);

    fuse_kernel<<<4096, 512>>>((const float4*)feat, (const float4*)mem,
                               Wmax, bmax, Wscore, bscore);
    community_kernel<<<GRID_CTAS, 512, SMEM_BYTES>>>(Wscore, Wfit, bfit,
                                                     out_cluster, out_scores, out_fit, nbrs);
}

// round 9
// speedup vs baseline: 1.2948x; 1.0057x over previous
#include <cuda_runtime.h>
#include <cuda_fp16.h>
#include <math_constants.h>
#include <cstdint>

#define C_DIM 128
#define D_DEG 64
#define NODE_NUM 8192
#define N_TOTAL 200000
#define NEG_SLOPE 0.2f
#define GRID_CTAS 296        // 2 persistent CTAs per SM
#define GROUPS 4             // independent 128-thread groups per CTA
#define GSTREAMS (GRID_CTAS * GROUPS)   // 1184 node streams

// smem layout (dynamic)
#define OFF_STAGE 0                 // [4][64][128] fp16 = 64KB (warp-private rows)
#define OFF_PARTA 65536             // [4][4][128] f32 colmax partials = 8KB
#define OFF_PARTP 73728             // [4][4][128] f32 pool  partials = 8KB
#define OFF_SRAW  81920             // [4][64] f32
#define OFF_WRED  82944             // [4][4]  f32
#define SMEM_BYTES 83008

// Fused fp16 table: S[n][c] = fp16(feat[n][c] + mem[n][c]); 51.2MB static scratch.
__device__ __half2 g_S[(size_t)N_TOTAL * (C_DIM / 2)];
// Folded weights: v = W_max @ W_score[:128]; c0 = dot(b_max, W_score[:128]) + b_score
__device__ float g_v[C_DIM];
__device__ float g_c0;

// ---- Kernel 1: streaming fuse (feat+mem -> fp16 S) + weight folding ----
__global__ __launch_bounds__(512)
void fuse_kernel(const float4* __restrict__ feat4,
                 const float4* __restrict__ mem4,
                 const float* __restrict__ Wmax,
                 const float* __restrict__ bmax,
                 const float* __restrict__ Wscore,
                 const float* __restrict__ bscore) {
    if (blockIdx.x == 0) {
        __shared__ float ws1[C_DIM];
        int t = threadIdx.x;
        if (t < C_DIM) ws1[t] = Wscore[t];
        __syncthreads();
        if (t < C_DIM) {
            const float* row = Wmax + t * C_DIM;
            float acc = 0.f;
#pragma unroll 8
            for (int k = 0; k < C_DIM; k++) acc += row[k] * ws1[k];
            g_v[t] = acc;
            if (t == 0) {
                float c0 = bscore[0];
                for (int k = 0; k < C_DIM; k++) c0 += bmax[k] * ws1[k];
                g_c0 = c0;
            }
        }
    }
    // 16B store granularity: each iter fuses 8 floats -> 8 halfs
    uint4* gS4 = reinterpret_cast<uint4*>(g_S);
    const int total4 = N_TOTAL * (C_DIM / 8);   // 3.2M uint4 stores
    const int stride = gridDim.x * blockDim.x;
    for (int i = blockIdx.x * blockDim.x + threadIdx.x; i < total4; i += stride) {
        float4 a0 = feat4[2 * i],     b0 = mem4[2 * i];
        float4 a1 = feat4[2 * i + 1], b1 = mem4[2 * i + 1];
        __half2 h0 = __floats2half2_rn(a0.x + b0.x, a0.y + b0.y);
        __half2 h1 = __floats2half2_rn(a0.z + b0.z, a0.w + b0.w);
        __half2 h2 = __floats2half2_rn(a1.x + b1.x, a1.y + b1.y);
        __half2 h3 = __floats2half2_rn(a1.z + b1.z, a1.w + b1.w);
        uint4 pack;
        pack.x = *reinterpret_cast<unsigned int*>(&h0);
        pack.y = *reinterpret_cast<unsigned int*>(&h1);
        pack.z = *reinterpret_cast<unsigned int*>(&h2);
        pack.w = *reinterpret_cast<unsigned int*>(&h3);
        gS4[i] = pack;
    }
}

__device__ __forceinline__ void cp16(unsigned int dst, const void* src) {
    asm volatile("cp.async.cg.shared.global [%0], [%1], 16;\n"
                 :: "r"(dst), "l"(src) : "memory");
}
__device__ __forceinline__ void gbar(int id) {
    asm volatile("bar.sync %0, 128;" :: "r"(id) : "memory");
}

// ---- Kernel 2: 4 warpgroup pipelines, warp-private staging, 2 barriers/node ----
__global__ __launch_bounds__(512, 2)
void community_kernel(const float* __restrict__ Wscore,
                      const float* __restrict__ Wfit,
                      const float* __restrict__ bfit,
                      float* __restrict__ out_cluster,   // [NODE_NUM, C]
                      float* __restrict__ out_scores,    // [NODE_NUM, D]
                      float* __restrict__ out_fit,       // [NODE_NUM]
                      const int* __restrict__ neighbors)
{
    extern __shared__ char smem[];

    const int t    = threadIdx.x;
    const int lane = t & 31;
    const int wid  = t >> 5;     // 0..15
    const int g    = wid >> 2;   // group 0..3
    const int gw   = wid & 3;    // warp within group
    const int tg   = t & 127;    // thread within group
    const int barid = g + 1;

    char*  stg_b = smem + OFF_STAGE + g * 16384;              // group stage, bytes
    __half2* stg = (__half2*)stg_b;                           // [64][64] half2
    float* partA = (float*)(smem + OFF_PARTA) + g * 512;      // colmax partials
    float* partP = (float*)(smem + OFF_PARTP) + g * 512;      // pool partials
    float* srawg = (float*)(smem + OFF_SRAW) + g * 64;
    float* wredg = (float*)(smem + OFF_WRED) + g * 4;
    const unsigned int stg_u = (unsigned int)__cvta_generic_to_shared(stg_b);
    const char* Sbase = (const char*)g_S;

    // loop-invariant weights
    const float4 w2v   = *reinterpret_cast<const float4*>(Wscore + C_DIM + 4 * lane);
    const float4 gv4   = *reinterpret_cast<const float4*>(g_v + 4 * lane);
    const float  wfitv = Wfit[tg];
    const float  bfitv = bfit[0];
    const float  c0    = g_c0;

    int node = blockIdx.x * GROUPS + g;
    int prev = -1;

    // ---- prologue: warp stages its OWN 16 rows of first node ----
#pragma unroll
    for (int i = 0; i < 8; i++) {
        int c  = lane + 32 * i;          // 0..255: chunk within warp's 16 rows
        int r  = c >> 4, ch = c & 15;
        int row = gw * 16 + r;
        long long nid = neighbors[node * D_DEG + row];
        cp16(stg_u + (unsigned)(row * 256 + ch * 16), Sbase + nid * 256 + ch * 16);
    }
    asm volatile("cp.async.commit_group;\n" ::: "memory");

    while (true) {
        const int  next     = node + GSTREAMS;
        const bool has_next = (next < NODE_NUM);

        asm volatile("cp.async.wait_group 0;\n" ::: "memory");
        // stage is warp-private: no barrier needed before reading it.

        // ---- Phase A: per-row score dot + column max over own 16 rows ----
        float cm0 = -CUDART_INF_F, cm1 = -CUDART_INF_F, cm2 = -CUDART_INF_F, cm3 = -CUDART_INF_F;
#pragma unroll
        for (int r = 0; r < 16; r++) {
            int row = gw * 16 + r;
            uint2 u = *reinterpret_cast<const uint2*>(stg + row * 64 + lane * 2);
            __half2 h0 = *reinterpret_cast<__half2*>(&u.x);
            __half2 h1 = *reinterpret_cast<__half2*>(&u.y);
            float2 f0 = __half22float2(h0);
            float2 f1 = __half22float2(h1);
            cm0 = fmaxf(cm0, f0.x); cm1 = fmaxf(cm1, f0.y);
            cm2 = fmaxf(cm2, f1.x); cm3 = fmaxf(cm3, f1.y);
            float p = f0.x * w2v.x + f0.y * w2v.y + f1.x * w2v.z + f1.y * w2v.w;
#pragma unroll
            for (int o = 16; o > 0; o >>= 1) p += __shfl_xor_sync(0xffffffffu, p, o);
            if (lane == 0) srawg[row] = p;
        }
        *reinterpret_cast<float4*>(partA + gw * 128 + lane * 4) = make_float4(cm0, cm1, cm2, cm3);
        gbar(barid);   // B2: partA + sraw visible (also orders prev iter's wred writes)

        // ---- deferred fitness for previous node (ordered by B2) ----
        if (prev >= 0 && tg == 0) {
            float s = wredg[0] + wredg[1] + wredg[2] + wredg[3] + bfitv;
            out_fit[prev] = 1.f / (1.f + __expf(-s));
        }

        // ---- all warps redundantly: colmax-dot -> s_const ----
        float s_const;
        {
            float4 m0 = *reinterpret_cast<const float4*>(partA + 0   + lane * 4);
            float4 m1 = *reinterpret_cast<const float4*>(partA + 128 + lane * 4);
            float4 m2 = *reinterpret_cast<const float4*>(partA + 256 + lane * 4);
            float4 m3 = *reinterpret_cast<const float4*>(partA + 384 + lane * 4);
            float x = fmaxf(fmaxf(m0.x, m1.x), fmaxf(m2.x, m3.x));
            float y = fmaxf(fmaxf(m0.y, m1.y), fmaxf(m2.y, m3.y));
            float z = fmaxf(fmaxf(m0.z, m1.z), fmaxf(m2.z, m3.z));
            float w = fmaxf(fmaxf(m0.w, m1.w), fmaxf(m2.w, m3.w));
            float p = x * gv4.x + y * gv4.y + z * gv4.z + w * gv4.w;
#pragma unroll
            for (int o = 16; o > 0; o >>= 1) p += __shfl_xor_sync(0xffffffffu, p, o);
            s_const = p + c0;
        }

        // ---- all warps redundantly: leaky-relu + segment softmax (regs) ----
        float s0, s1;
        {
            float a0 = s_const + srawg[lane];
            float a1 = s_const + srawg[lane + 32];
            a0 = (a0 >= 0.f) ? a0 : NEG_SLOPE * a0;
            a1 = (a1 >= 0.f) ? a1 : NEG_SLOPE * a1;
            float mx = fmaxf(a0, a1);
#pragma unroll
            for (int o = 16; o > 0; o >>= 1) mx = fmaxf(mx, __shfl_xor_sync(0xffffffffu, mx, o));
            float e0 = __expf(a0 - mx), e1 = __expf(a1 - mx);
            float sm = e0 + e1;
#pragma unroll
            for (int o = 16; o > 0; o >>= 1) sm += __shfl_xor_sync(0xffffffffu, sm, o);
            float inv = 1.f / sm;
            s0 = e0 * inv;
            s1 = e1 * inv;
        }
        if (gw == 0) {
            out_scores[node * D_DEG + lane]      = s0;
            out_scores[node * D_DEG + lane + 32] = s1;
        }

        // ---- Phase D: weighted pooling over own 16 rows (scores via shfl) ----
        {
            const float sv = (gw < 2) ? s0 : s1;
            float a0 = 0.f, a1 = 0.f, a2 = 0.f, a3 = 0.f;
#pragma unroll
            for (int r = 0; r < 16; r++) {
                int row = gw * 16 + r;
                float sc = __shfl_sync(0xffffffffu, sv, (gw & 1) * 16 + r);
                uint2 u = *reinterpret_cast<const uint2*>(stg + row * 64 + lane * 2);
                __half2 h0 = *reinterpret_cast<__half2*>(&u.x);
                __half2 h1 = *reinterpret_cast<__half2*>(&u.y);
                float2 f0 = __half22float2(h0);
                float2 f1 = __half22float2(h1);
                a0 = fmaf(sc, f0.x, a0); a1 = fmaf(sc, f0.y, a1);
                a2 = fmaf(sc, f1.x, a2); a3 = fmaf(sc, f1.y, a3);
            }
            *reinterpret_cast<float4*>(partP + gw * 128 + lane * 4) = make_float4(a0, a1, a2, a3);
        }

        // ---- prefetch next node's own rows (stage warp-private: no barrier) ----
        if (has_next) {
#pragma unroll
            for (int i = 0; i < 8; i++) {
                int c  = lane + 32 * i;
                int r  = c >> 4, ch = c & 15;
                int row = gw * 16 + r;
                long long nid = neighbors[next * D_DEG + row];
                cp16(stg_u + (unsigned)(row * 256 + ch * 16), Sbase + nid * 256 + ch * 16);
            }
            asm volatile("cp.async.commit_group;\n" ::: "memory");
        }
        gbar(barid);   // B3: partP visible

        // ---- Phase E: cluster sum + output + fitness partials ----
        {
            float cf = partP[tg] + partP[128 + tg] + partP[256 + tg] + partP[384 + tg];
            out_cluster[node * C_DIM + tg] = cf;
            float p = cf * wfitv;
#pragma unroll
            for (int o = 16; o > 0; o >>= 1) p += __shfl_xor_sync(0xffffffffu, p, o);
            if (lane == 0) wredg[gw] = p;   // consumed after next iter's B2 (or tail)
        }

        prev = node;
        if (!has_next) break;
        node = next;
    }

    // ---- tail: final node's fitness ----
    gbar(barid);
    if (tg == 0) {
        float s = wredg[0] + wredg[1] + wredg[2] + wredg[3] + bfitv;
        out_fit[prev] = 1.f / (1.f + __expf(-s));
    }
}

extern "C" void kernel_launch(void* const* d_in, const int* in_sizes, int n_in,
                              void* d_out, int out_size) {
    const float* feat   = (const float*)d_in[0];
    const float* mem    = (const float*)d_in[1];
    const float* Wmax   = (const float*)d_in[2];
    const float* bmax   = (const float*)d_in[3];
    const float* Wscore = (const float*)d_in[4];
    const float* bscore = (const float*)d_in[5];
    const float* Wfit   = (const float*)d_in[6];
    const float* bfit   = (const float*)d_in[7];
    const int*   nbrs   = (const int*)d_in[8];

    float* out = (float*)d_out;
    float* out_cluster = out;                                        // 8192*128
    float* out_scores  = out + NODE_NUM * C_DIM;                     // 8192*64
    float* out_fit     = out + NODE_NUM * C_DIM + NODE_NUM * D_DEG;  // 8192

    cudaFuncSetAttribute(community_kernel,
                         cudaFuncAttributeMaxDynamicSharedMemorySize, SMEM_BYTES);

    fuse_kernel<<<4096, 512>>>((const float4*)feat, (const float4*)mem,
                               Wmax, bmax, Wscore, bscore);
    community_kernel<<<GRID_CTAS, 512, SMEM_BYTES>>>(Wscore, Wfit, bfit,
                                                     out_cluster, out_scores, out_fit, nbrs);
}

// round 10
// speedup vs baseline: 1.4193x; 1.0962x over previous
#include <cuda_runtime.h>
#include <cuda_fp16.h>
#include <math_constants.h>
#include <cstdint>

#define C_DIM 128
#define D_DEG 64
#define NODE_NUM 8192
#define N_TOTAL 200000
#define NEG_SLOPE 0.2f
#define GRID_CTAS 296        // 2 persistent CTAs per SM
#define GROUPS 4             // independent 128-thread groups per CTA
#define GSTREAMS (GRID_CTAS * GROUPS)   // 1184 node streams

// smem layout (dynamic)
#define OFF_STAGE 0                 // [4][64][128] fp16 = 64KB (warp-private rows)
#define OFF_PARTA 65536             // [4][4][32] uint2 fp16 colmax partials = 4KB
#define OFF_PARTP 69632             // [4][4][128] f32 pool partials = 8KB
#define OFF_SRAW  77824             // [4][64] f32 = 1KB
#define OFF_WRED  78848             // [4][4] f32
#define SMEM_BYTES 78912

// Fused fp16 table: S[n][c] = fp16(feat[n][c] + mem[n][c]); 51.2MB static scratch.
__device__ __half2 g_S[(size_t)N_TOTAL * (C_DIM / 2)];
// Folded weights: v = W_max @ W_score[:128]; c0 = dot(b_max, W_score[:128]) + b_score
__device__ float g_v[C_DIM];
__device__ float g_c0;

// ---- Kernel 1: streaming fuse (feat+mem -> fp16 S) + weight folding ----
__global__ __launch_bounds__(512)
void fuse_kernel(const float4* __restrict__ feat4,
                 const float4* __restrict__ mem4,
                 const float* __restrict__ Wmax,
                 const float* __restrict__ bmax,
                 const float* __restrict__ Wscore,
                 const float* __restrict__ bscore) {
    if (blockIdx.x == 0) {
        __shared__ float ws1[C_DIM];
        int t = threadIdx.x;
        if (t < C_DIM) ws1[t] = Wscore[t];
        __syncthreads();
        if (t < C_DIM) {
            const float* row = Wmax + t * C_DIM;
            float acc = 0.f;
#pragma unroll 8
            for (int k = 0; k < C_DIM; k++) acc += row[k] * ws1[k];
            g_v[t] = acc;
            if (t == 0) {
                float c0 = bscore[0];
                for (int k = 0; k < C_DIM; k++) c0 += bmax[k] * ws1[k];
                g_c0 = c0;
            }
        }
    }
    uint4* gS4 = reinterpret_cast<uint4*>(g_S);
    const int total4 = N_TOTAL * (C_DIM / 8);   // 3.2M uint4 stores
    const int stride = gridDim.x * blockDim.x;
    for (int i = blockIdx.x * blockDim.x + threadIdx.x; i < total4; i += stride) {
        float4 a0 = feat4[2 * i],     b0 = mem4[2 * i];
        float4 a1 = feat4[2 * i + 1], b1 = mem4[2 * i + 1];
        __half2 h0 = __floats2half2_rn(a0.x + b0.x, a0.y + b0.y);
        __half2 h1 = __floats2half2_rn(a0.z + b0.z, a0.w + b0.w);
        __half2 h2 = __floats2half2_rn(a1.x + b1.x, a1.y + b1.y);
        __half2 h3 = __floats2half2_rn(a1.z + b1.z, a1.w + b1.w);
        uint4 pack;
        pack.x = *reinterpret_cast<unsigned int*>(&h0);
        pack.y = *reinterpret_cast<unsigned int*>(&h1);
        pack.z = *reinterpret_cast<unsigned int*>(&h2);
        pack.w = *reinterpret_cast<unsigned int*>(&h3);
        gS4[i] = pack;
    }
}

__device__ __forceinline__ void cp16(unsigned int dst, const void* src) {
    asm volatile("cp.async.cg.shared.global [%0], [%1], 16;\n"
                 :: "r"(dst), "l"(src) : "memory");
}
__device__ __forceinline__ void gbar(int id) {
    asm volatile("bar.sync %0, 128;" :: "r"(id) : "memory");
}
__device__ __forceinline__ __half2 u2h(unsigned int u) {
    return *reinterpret_cast<__half2*>(&u);
}

// ---- Kernel 2: 4 warpgroup pipelines, paired reductions, fp16 colmax ----
__global__ __launch_bounds__(512, 2)
void community_kernel(const float* __restrict__ Wscore,
                      const float* __restrict__ Wfit,
                      const float* __restrict__ bfit,
                      float* __restrict__ out_cluster,   // [NODE_NUM, C]
                      float* __restrict__ out_scores,    // [NODE_NUM, D]
                      float* __restrict__ out_fit,       // [NODE_NUM]
                      const int* __restrict__ neighbors)
{
    extern __shared__ char smem[];

    const int t    = threadIdx.x;
    const int lane = t & 31;
    const int wid  = t >> 5;     // 0..15
    const int g    = wid >> 2;   // group 0..3
    const int gw   = wid & 3;    // warp within group
    const int tg   = t & 127;    // thread within group
    const int barid = g + 1;

    char*  stg_b = smem + OFF_STAGE + g * 16384;                // group stage, bytes
    __half2* stg = (__half2*)stg_b;                             // [64][64] half2
    uint2* partA = (uint2*)(smem + OFF_PARTA) + g * 128;        // [4][32] fp16 colmax
    float* partP = (float*)(smem + OFF_PARTP) + g * 512;        // pool partials
    float* srawg = (float*)(smem + OFF_SRAW) + g * 64;
    float* wredg = (float*)(smem + OFF_WRED) + g * 4;
    const unsigned int stg_u = (unsigned int)__cvta_generic_to_shared(stg_b);
    const char* Sbase = (const char*)g_S;

    // loop-invariant weights
    const float4 w2v   = *reinterpret_cast<const float4*>(Wscore + C_DIM + 4 * lane);
    const float4 gv4   = *reinterpret_cast<const float4*>(g_v + 4 * lane);
    const float  wfitv = Wfit[tg];
    const float  bfitv = bfit[0];
    const float  c0    = g_c0;
    const __half2 NEGINF2 = __halves2half2(__ushort_as_half(0xFC00u),
                                           __ushort_as_half(0xFC00u));

    int node = blockIdx.x * GROUPS + g;
    int prev = -1;

    // ---- prologue: warp stages its OWN 16 rows (ids: 1 LDG + shfl) ----
    {
        int myid = 0;
        if (lane < 16) myid = neighbors[node * D_DEG + gw * 16 + lane];
#pragma unroll
        for (int i = 0; i < 8; i++) {
            int c  = lane + 32 * i;          // chunk within warp's 16 rows
            int r  = c >> 4, ch = c & 15;
            long long nid = __shfl_sync(0xffffffffu, myid, r);
            int row = gw * 16 + r;
            cp16(stg_u + (unsigned)(row * 256 + ch * 16), Sbase + nid * 256 + ch * 16);
        }
        asm volatile("cp.async.commit_group;\n" ::: "memory");
    }

    while (true) {
        const int  next     = node + GSTREAMS;
        const bool has_next = (next < NODE_NUM);

        asm volatile("cp.async.wait_group 0;\n" ::: "memory");
        // stage is warp-private: no barrier needed before reading it.

        // ---- Phase A: paired row-dot reduction + fp16 colmax over own 16 rows ----
        __half2 cmx0 = NEGINF2, cmx1 = NEGINF2;
#pragma unroll
        for (int k = 0; k < 8; k++) {
            int row0 = gw * 16 + 2 * k;
            uint2 u0 = *reinterpret_cast<const uint2*>(stg + row0 * 64 + lane * 2);
            uint2 u1 = *reinterpret_cast<const uint2*>(stg + (row0 + 1) * 64 + lane * 2);
            __half2 a00 = u2h(u0.x), a01 = u2h(u0.y);
            __half2 a10 = u2h(u1.x), a11 = u2h(u1.y);
            cmx0 = __hmax2(cmx0, __hmax2(a00, a10));
            cmx1 = __hmax2(cmx1, __hmax2(a01, a11));
            float2 f00 = __half22float2(a00), f01 = __half22float2(a01);
            float2 f10 = __half22float2(a10), f11 = __half22float2(a11);
            float p0 = f00.x * w2v.x + f00.y * w2v.y + f01.x * w2v.z + f01.y * w2v.w;
            float p1 = f10.x * w2v.x + f10.y * w2v.y + f11.x * w2v.z + f11.y * w2v.w;
            // paired reduction: mix rows into parity lanes, then 4 common stages
            float q0 = __shfl_xor_sync(0xffffffffu, p0, 1);
            float q1 = __shfl_xor_sync(0xffffffffu, p1, 1);
            float v = (lane & 1) ? (p1 + q1) : (p0 + q0);
#pragma unroll
            for (int o = 2; o <= 16; o <<= 1) v += __shfl_xor_sync(0xffffffffu, v, o);
            if (lane < 2) srawg[row0 + lane] = v;   // lane0->row0, lane1->row1
        }
        partA[gw * 32 + lane] = make_uint2(*reinterpret_cast<unsigned int*>(&cmx0),
                                           *reinterpret_cast<unsigned int*>(&cmx1));
        gbar(barid);   // B2: partA + sraw visible (also orders prev iter's wred writes)

        // ---- deferred fitness for previous node (ordered by B2) ----
        if (prev >= 0 && tg == 0) {
            float s = wredg[0] + wredg[1] + wredg[2] + wredg[3] + bfitv;
            out_fit[prev] = 1.f / (1.f + __expf(-s));
        }

        // ---- all warps redundantly: fp16 colmax combine -> dot(g_v) -> s_const ----
        float s_const;
        {
            uint2 m0 = partA[0   + lane], m1 = partA[32  + lane];
            uint2 m2 = partA[64  + lane], m3 = partA[96  + lane];
            __half2 x0 = __hmax2(__hmax2(u2h(m0.x), u2h(m1.x)),
                                 __hmax2(u2h(m2.x), u2h(m3.x)));
            __half2 x1 = __hmax2(__hmax2(u2h(m0.y), u2h(m1.y)),
                                 __hmax2(u2h(m2.y), u2h(m3.y)));
            float2 c01 = __half22float2(x0);
            float2 c23 = __half22float2(x1);
            float p = c01.x * gv4.x + c01.y * gv4.y + c23.x * gv4.z + c23.y * gv4.w;
#pragma unroll
            for (int o = 16; o > 0; o >>= 1) p += __shfl_xor_sync(0xffffffffu, p, o);
            s_const = p + c0;
        }

        // ---- all warps redundantly: leaky-relu + segment softmax (regs) ----
        float s0, s1;
        {
            float a0 = s_const + srawg[lane];
            float a1 = s_const + srawg[lane + 32];
            a0 = (a0 >= 0.f) ? a0 : NEG_SLOPE * a0;
            a1 = (a1 >= 0.f) ? a1 : NEG_SLOPE * a1;
            float mx = fmaxf(a0, a1);
#pragma unroll
            for (int o = 16; o > 0; o >>= 1) mx = fmaxf(mx, __shfl_xor_sync(0xffffffffu, mx, o));
            float e0 = __expf(a0 - mx), e1 = __expf(a1 - mx);
            float sm = e0 + e1;
#pragma unroll
            for (int o = 16; o > 0; o >>= 1) sm += __shfl_xor_sync(0xffffffffu, sm, o);
            float inv = 1.f / sm;
            s0 = e0 * inv;
            s1 = e1 * inv;
        }
        if (gw == 0) {
            out_scores[node * D_DEG + lane]      = s0;
            out_scores[node * D_DEG + lane + 32] = s1;
        }

        // ---- Phase D: weighted pooling over own 16 rows (scores via shfl) ----
        {
            const float sv = (gw < 2) ? s0 : s1;
            float a0 = 0.f, a1 = 0.f, a2 = 0.f, a3 = 0.f;
#pragma unroll
            for (int r = 0; r < 16; r++) {
                int row = gw * 16 + r;
                float sc = __shfl_sync(0xffffffffu, sv, (gw & 1) * 16 + r);
                uint2 u = *reinterpret_cast<const uint2*>(stg + row * 64 + lane * 2);
                float2 f0 = __half22float2(u2h(u.x));
                float2 f1 = __half22float2(u2h(u.y));
                a0 = fmaf(sc, f0.x, a0); a1 = fmaf(sc, f0.y, a1);
                a2 = fmaf(sc, f1.x, a2); a3 = fmaf(sc, f1.y, a3);
            }
            *reinterpret_cast<float4*>(partP + gw * 128 + lane * 4) = make_float4(a0, a1, a2, a3);
        }

        // ---- prefetch next node's own rows (stage warp-private: no barrier) ----
        if (has_next) {
            int myid = 0;
            if (lane < 16) myid = neighbors[next * D_DEG + gw * 16 + lane];
#pragma unroll
            for (int i = 0; i < 8; i++) {
                int c  = lane + 32 * i;
                int r  = c >> 4, ch = c & 15;
                long long nid = __shfl_sync(0xffffffffu, myid, r);
                int row = gw * 16 + r;
                cp16(stg_u + (unsigned)(row * 256 + ch * 16), Sbase + nid * 256 + ch * 16);
            }
            asm volatile("cp.async.commit_group;\n" ::: "memory");
        }
        gbar(barid);   // B3: partP visible

        // ---- Phase E: cluster sum + output + fitness partials ----
        {
            float cf = partP[tg] + partP[128 + tg] + partP[256 + tg] + partP[384 + tg];
            out_cluster[node * C_DIM + tg] = cf;
            float p = cf * wfitv;
#pragma unroll
            for (int o = 16; o > 0; o >>= 1) p += __shfl_xor_sync(0xffffffffu, p, o);
            if (lane == 0) wredg[gw] = p;   // consumed after next iter's B2 (or tail)
        }

        prev = node;
        if (!has_next) break;
        node = next;
    }

    // ---- tail: final node's fitness ----
    gbar(barid);
    if (tg == 0) {
        float s = wredg[0] + wredg[1] + wredg[2] + wredg[3] + bfitv;
        out_fit[prev] = 1.f / (1.f + __expf(-s));
    }
}

extern "C" void kernel_launch(void* const* d_in, const int* in_sizes, int n_in,
                              void* d_out, int out_size) {
    const float* feat   = (const float*)d_in[0];
    const float* mem    = (const float*)d_in[1];
    const float* Wmax   = (const float*)d_in[2];
    const float* bmax   = (const float*)d_in[3];
    const float* Wscore = (const float*)d_in[4];
    const float* bscore = (const float*)d_in[5];
    const float* Wfit   = (const float*)d_in[6];
    const float* bfit   = (const float*)d_in[7];
    const int*   nbrs   = (const int*)d_in[8];

    float* out = (float*)d_out;
    float* out_cluster = out;                                        // 8192*128
    float* out_scores  = out + NODE_NUM * C_DIM;                     // 8192*64
    float* out_fit     = out + NODE_NUM * C_DIM + NODE_NUM * D_DEG;  // 8192

    cudaFuncSetAttribute(community_kernel,
                         cudaFuncAttributeMaxDynamicSharedMemorySize, SMEM_BYTES);

    fuse_kernel<<<4096, 512>>>((const float4*)feat, (const float4*)mem,
                               Wmax, bmax, Wscore, bscore);
    community_kernel<<<GRID_CTAS, 512, SMEM_BYTES>>>(Wscore, Wfit, bfit,
                                                     out_cluster, out_scores, out_fit, nbrs);
}

// round 11
// speedup vs baseline: 1.4482x; 1.0204x over previous
#include <cuda_runtime.h>
#include <cuda_fp16.h>
#include <math_constants.h>
#include <cstdint>

#define C_DIM 128
#define D_DEG 64
#define NODE_NUM 8192
#define N_TOTAL 200000
#define NEG_SLOPE 0.2f
#define GRID_CTAS 296        // 2 persistent CTAs per SM
#define GROUPS 4             // independent 128-thread groups per CTA
#define GSTREAMS (GRID_CTAS * GROUPS)   // 1184 node streams

// smem layout (dynamic)
#define OFF_STAGE 0                 // [4][64][128] fp16 = 64KB (warp-private rows)
#define OFF_PARTA 65536             // [4][4][32] uint2 fp16 colmax partials = 4KB
#define OFF_PARTP 69632             // [4][4][128] f32 pool partials = 8KB
#define OFF_SRAW  77824             // [4][64] f32 = 1KB
#define OFF_SARR  78848             // [4][64] f32 = 1KB
#define OFF_WRED  79872             // [4][4] f32
#define SMEM_BYTES 79936

// Fused fp16 table: S[n][c] = fp16(feat[n][c] + mem[n][c]); 51.2MB static scratch.
__device__ __half2 g_S[(size_t)N_TOTAL * (C_DIM / 2)];
// Folded weights: v = W_max @ W_score[:128]; c0 = dot(b_max, W_score[:128]) + b_score
__device__ float g_v[C_DIM];
__device__ float g_c0;

// ---- Kernel 1: streaming fuse (feat+mem -> fp16 S) + weight folding ----
__global__ __launch_bounds__(512)
void fuse_kernel(const float4* __restrict__ feat4,
                 const float4* __restrict__ mem4,
                 const float* __restrict__ Wmax,
                 const float* __restrict__ bmax,
                 const float* __restrict__ Wscore,
                 const float* __restrict__ bscore) {
    if (blockIdx.x == 0) {
        __shared__ float ws1[C_DIM];
        int t = threadIdx.x;
        if (t < C_DIM) ws1[t] = Wscore[t];
        __syncthreads();
        if (t < C_DIM) {
            const float* row = Wmax + t * C_DIM;
            float acc = 0.f;
#pragma unroll 8
            for (int k = 0; k < C_DIM; k++) acc += row[k] * ws1[k];
            g_v[t] = acc;
            if (t == 0) {
                float c0 = bscore[0];
                for (int k = 0; k < C_DIM; k++) c0 += bmax[k] * ws1[k];
                g_c0 = c0;
            }
        }
    }
    uint4* gS4 = reinterpret_cast<uint4*>(g_S);
    const int total4 = N_TOTAL * (C_DIM / 8);   // 3.2M uint4 stores
    const int stride = gridDim.x * blockDim.x;
    for (int i = blockIdx.x * blockDim.x + threadIdx.x; i < total4; i += stride) {
        float4 a0 = feat4[2 * i],     b0 = mem4[2 * i];
        float4 a1 = feat4[2 * i + 1], b1 = mem4[2 * i + 1];
        __half2 h0 = __floats2half2_rn(a0.x + b0.x, a0.y + b0.y);
        __half2 h1 = __floats2half2_rn(a0.z + b0.z, a0.w + b0.w);
        __half2 h2 = __floats2half2_rn(a1.x + b1.x, a1.y + b1.y);
        __half2 h3 = __floats2half2_rn(a1.z + b1.z, a1.w + b1.w);
        uint4 pack;
        pack.x = *reinterpret_cast<unsigned int*>(&h0);
        pack.y = *reinterpret_cast<unsigned int*>(&h1);
        pack.z = *reinterpret_cast<unsigned int*>(&h2);
        pack.w = *reinterpret_cast<unsigned int*>(&h3);
        gS4[i] = pack;
    }
}

__device__ __forceinline__ void cp16(unsigned int dst, const void* src) {
    asm volatile("cp.async.cg.shared.global [%0], [%1], 16;\n"
                 :: "r"(dst), "l"(src) : "memory");
}
__device__ __forceinline__ void gbar(int id) {
    asm volatile("bar.sync %0, 128;" :: "r"(id) : "memory");
}
__device__ __forceinline__ __half2 u2h(unsigned int u) {
    return *reinterpret_cast<__half2*>(&u);
}

// ---- Kernel 2: 4 warpgroup pipelines; quad reductions; single-warp softmax;
//      prefetch interleaved into pooling ----
__global__ __launch_bounds__(512, 2)
void community_kernel(const float* __restrict__ Wscore,
                      const float* __restrict__ Wfit,
                      const float* __restrict__ bfit,
                      float* __restrict__ out_cluster,   // [NODE_NUM, C]
                      float* __restrict__ out_scores,    // [NODE_NUM, D]
                      float* __restrict__ out_fit,       // [NODE_NUM]
                      const int* __restrict__ neighbors)
{
    extern __shared__ char smem[];

    const int t    = threadIdx.x;
    const int lane = t & 31;
    const int wid  = t >> 5;     // 0..15
    const int g    = wid >> 2;   // group 0..3
    const int gw   = wid & 3;    // warp within group
    const int tg   = t & 127;    // thread within group
    const int barid = g + 1;

    char*  stg_b = smem + OFF_STAGE + g * 16384;                // group stage, bytes
    __half2* stg = (__half2*)stg_b;                             // [64][64] half2
    uint2* partA = (uint2*)(smem + OFF_PARTA) + g * 128;        // [4][32] fp16 colmax
    float* partP = (float*)(smem + OFF_PARTP) + g * 512;        // pool partials
    float* srawg = (float*)(smem + OFF_SRAW) + g * 64;
    float* sarrg = (float*)(smem + OFF_SARR) + g * 64;
    float* wredg = (float*)(smem + OFF_WRED) + g * 4;
    const unsigned int stg_u = (unsigned int)__cvta_generic_to_shared(stg_b);
    const char* Sbase = (const char*)g_S;

    // loop-invariant weights
    const float4 w2v   = *reinterpret_cast<const float4*>(Wscore + C_DIM + 4 * lane);
    const float4 gv4   = *reinterpret_cast<const float4*>(g_v + 4 * lane);
    const float  wfitv = Wfit[tg];
    const float  bfitv = bfit[0];
    const float  c0    = g_c0;
    const __half2 NEGINF2 = __halves2half2(__ushort_as_half(0xFC00u),
                                           __ushort_as_half(0xFC00u));

    int node = blockIdx.x * GROUPS + g;
    int prev = -1;

    // ---- prologue: warp stages its OWN 16 rows (ids: 1 LDG + shfl) ----
    {
        int myid = 0;
        if (lane < 16) myid = neighbors[node * D_DEG + gw * 16 + lane];
#pragma unroll
        for (int i = 0; i < 8; i++) {
            int c  = lane + 32 * i;          // chunk within warp's 16 rows
            int r  = c >> 4, ch = c & 15;
            long long nid = __shfl_sync(0xffffffffu, myid, r);
            int row = gw * 16 + r;
            cp16(stg_u + (unsigned)(row * 256 + ch * 16), Sbase + nid * 256 + ch * 16);
        }
        asm volatile("cp.async.commit_group;\n" ::: "memory");
    }

    while (true) {
        const int  next     = node + GSTREAMS;
        const bool has_next = (next < NODE_NUM);

        asm volatile("cp.async.wait_group 0;\n" ::: "memory");
        // stage is warp-private: no barrier needed before reading it.

        // ---- Phase A: quad row-dot reduction + fp16 colmax over own 16 rows ----
        __half2 cmx0 = NEGINF2, cmx1 = NEGINF2;
#pragma unroll
        for (int k = 0; k < 4; k++) {
            int r0 = gw * 16 + 4 * k;
            uint2 u0 = *reinterpret_cast<const uint2*>(stg + (r0 + 0) * 64 + lane * 2);
            uint2 u1 = *reinterpret_cast<const uint2*>(stg + (r0 + 1) * 64 + lane * 2);
            uint2 u2 = *reinterpret_cast<const uint2*>(stg + (r0 + 2) * 64 + lane * 2);
            uint2 u3 = *reinterpret_cast<const uint2*>(stg + (r0 + 3) * 64 + lane * 2);
            __half2 a0x = u2h(u0.x), a0y = u2h(u0.y);
            __half2 a1x = u2h(u1.x), a1y = u2h(u1.y);
            __half2 a2x = u2h(u2.x), a2y = u2h(u2.y);
            __half2 a3x = u2h(u3.x), a3y = u2h(u3.y);
            cmx0 = __hmax2(cmx0, __hmax2(__hmax2(a0x, a1x), __hmax2(a2x, a3x)));
            cmx1 = __hmax2(cmx1, __hmax2(__hmax2(a0y, a1y), __hmax2(a2y, a3y)));
            float2 f0x = __half22float2(a0x), f0y = __half22float2(a0y);
            float2 f1x = __half22float2(a1x), f1y = __half22float2(a1y);
            float2 f2x = __half22float2(a2x), f2y = __half22float2(a2y);
            float2 f3x = __half22float2(a3x), f3y = __half22float2(a3y);
            float p0 = f0x.x * w2v.x + f0x.y * w2v.y + f0y.x * w2v.z + f0y.y * w2v.w;
            float p1 = f1x.x * w2v.x + f1x.y * w2v.y + f1y.x * w2v.z + f1y.y * w2v.w;
            float p2 = f2x.x * w2v.x + f2x.y * w2v.y + f2y.x * w2v.z + f2y.y * w2v.w;
            float p3 = f3x.x * w2v.x + f3x.y * w2v.y + f3y.x * w2v.z + f3y.y * w2v.w;
            // quad butterfly: lane%4 == m ends with row r0+m's full dot
            float tA = (lane & 1) ? p0 : p1;
            tA = __shfl_xor_sync(0xffffffffu, tA, 1);
            float v01 = ((lane & 1) ? p1 : p0) + tA;
            float tB = (lane & 1) ? p2 : p3;
            tB = __shfl_xor_sync(0xffffffffu, tB, 1);
            float v23 = ((lane & 1) ? p3 : p2) + tB;
            float tC = (lane & 2) ? v01 : v23;
            tC = __shfl_xor_sync(0xffffffffu, tC, 2);
            float v = ((lane & 2) ? v23 : v01) + tC;
            v += __shfl_xor_sync(0xffffffffu, v, 4);
            v += __shfl_xor_sync(0xffffffffu, v, 8);
            v += __shfl_xor_sync(0xffffffffu, v, 16);
            if (lane < 4) srawg[r0 + lane] = v;
        }
        partA[gw * 32 + lane] = make_uint2(*reinterpret_cast<unsigned int*>(&cmx0),
                                           *reinterpret_cast<unsigned int*>(&cmx1));
        gbar(barid);   // B2: partA + sraw visible (also orders prev iter's wred writes)

        // ---- deferred fitness for previous node (ordered by B2) ----
        if (prev >= 0 && tg == 0) {
            float s = wredg[0] + wredg[1] + wredg[2] + wredg[3] + bfitv;
            out_fit[prev] = 1.f / (1.f + __expf(-s));
        }

        // ---- warp 0 only: colmax combine -> s_const -> softmax -> sarr ----
        if (gw == 0) {
            uint2 m0 = partA[0   + lane], m1 = partA[32  + lane];
            uint2 m2 = partA[64  + lane], m3 = partA[96  + lane];
            __half2 x0 = __hmax2(__hmax2(u2h(m0.x), u2h(m1.x)),
                                 __hmax2(u2h(m2.x), u2h(m3.x)));
            __half2 x1 = __hmax2(__hmax2(u2h(m0.y), u2h(m1.y)),
                                 __hmax2(u2h(m2.y), u2h(m3.y)));
            float2 c01 = __half22float2(x0);
            float2 c23 = __half22float2(x1);
            float p = c01.x * gv4.x + c01.y * gv4.y + c23.x * gv4.z + c23.y * gv4.w;
#pragma unroll
            for (int o = 16; o > 0; o >>= 1) p += __shfl_xor_sync(0xffffffffu, p, o);
            const float s_const = p + c0;

            float a0 = s_const + srawg[lane];
            float a1 = s_const + srawg[lane + 32];
            a0 = (a0 >= 0.f) ? a0 : NEG_SLOPE * a0;
            a1 = (a1 >= 0.f) ? a1 : NEG_SLOPE * a1;
            float mx = fmaxf(a0, a1);
#pragma unroll
            for (int o = 16; o > 0; o >>= 1) mx = fmaxf(mx, __shfl_xor_sync(0xffffffffu, mx, o));
            float e0 = __expf(a0 - mx), e1 = __expf(a1 - mx);
            float sm = e0 + e1;
#pragma unroll
            for (int o = 16; o > 0; o >>= 1) sm += __shfl_xor_sync(0xffffffffu, sm, o);
            float inv = 1.f / sm;
            float s0 = e0 * inv, s1 = e1 * inv;
            sarrg[lane]      = s0;
            sarrg[lane + 32] = s1;
            out_scores[node * D_DEG + lane]      = s0;
            out_scores[node * D_DEG + lane + 32] = s1;
        }
        gbar(barid);   // B3: sarr ready

        // ---- next-node ids (loaded early, consumed in D's interleaved prefetch) ----
        int myid2 = 0;
        if (has_next && lane < 16) myid2 = neighbors[next * D_DEG + gw * 16 + lane];

        // ---- Phase D: weighted pooling; prefetch interleaved every 2 rows ----
        {
            float a0 = 0.f, a1 = 0.f, a2 = 0.f, a3 = 0.f;
#pragma unroll
            for (int r = 0; r < 16; r++) {
                int row = gw * 16 + r;
                float sc = sarrg[row];   // LDS broadcast
                uint2 u = *reinterpret_cast<const uint2*>(stg + row * 64 + lane * 2);
                float2 f0 = __half22float2(u2h(u.x));
                float2 f1 = __half22float2(u2h(u.y));
                a0 = fmaf(sc, f0.x, a0); a1 = fmaf(sc, f0.y, a1);
                a2 = fmaf(sc, f1.x, a2); a3 = fmaf(sc, f1.y, a3);
                // after the odd row of each pair is consumed, refill that pair
                if ((r & 1) && has_next) {
                    int pair = r >> 1;                  // 0..7
                    int c  = pair * 32 + lane;          // chunk id 0..255
                    int rr = c >> 4, ch = c & 15;       // rr in {2*pair, 2*pair+1} <= r
                    long long nid = __shfl_sync(0xffffffffu, myid2, rr);
                    int wrow = gw * 16 + rr;
                    cp16(stg_u + (unsigned)(wrow * 256 + ch * 16),
                         Sbase + nid * 256 + ch * 16);
                }
            }
            if (has_next) asm volatile("cp.async.commit_group;\n" ::: "memory");
            *reinterpret_cast<float4*>(partP + gw * 128 + lane * 4) = make_float4(a0, a1, a2, a3);
        }
        gbar(barid);   // B4: partP visible

        // ---- Phase E: cluster sum + output + fitness partials ----
        {
            float cf = partP[tg] + partP[128 + tg] + partP[256 + tg] + partP[384 + tg];
            out_cluster[node * C_DIM + tg] = cf;
            float p = cf * wfitv;
#pragma unroll
            for (int o = 16; o > 0; o >>= 1) p += __shfl_xor_sync(0xffffffffu, p, o);
            if (lane == 0) wredg[gw] = p;   // consumed after next iter's B2 (or tail)
        }

        prev = node;
        if (!has_next) break;
        node = next;
    }

    // ---- tail: final node's fitness ----
    gbar(barid);
    if (tg == 0) {
        float s = wredg[0] + wredg[1] + wredg[2] + wredg[3] + bfitv;
        out_fit[prev] = 1.f / (1.f + __expf(-s));
    }
}

extern "C" void kernel_launch(void* const* d_in, const int* in_sizes, int n_in,
                              void* d_out, int out_size) {
    const float* feat   = (const float*)d_in[0];
    const float* mem    = (const float*)d_in[1];
    const float* Wmax   = (const float*)d_in[2];
    const float* bmax   = (const float*)d_in[3];
    const float* Wscore = (const float*)d_in[4];
    const float* bscore = (const float*)d_in[5];
    const float* Wfit   = (const float*)d_in[6];
    const float* bfit   = (const float*)d_in[7];
    const int*   nbrs   = (const int*)d_in[8];

    float* out = (float*)d_out;
    float* out_cluster = out;                                        // 8192*128
    float* out_scores  = out + NODE_NUM * C_DIM;                     // 8192*64
    float* out_fit     = out + NODE_NUM * C_DIM + NODE_NUM * D_DEG;  // 8192

    cudaFuncSetAttribute(community_kernel,
                         cudaFuncAttributeMaxDynamicSharedMemorySize, SMEM_BYTES);

    fuse_kernel<<<4096, 512>>>((const float4*)feat, (const float4*)mem,
                               Wmax, bmax, Wscore, bscore);
    community_kernel<<<GRID_CTAS, 512, SMEM_BYTES>>>(Wscore, Wfit, bfit,
                                                     out_cluster, out_scores, out_fit, nbrs);
}

// round 12
// speedup vs baseline: 1.5054x; 1.0395x over previous
#include <cuda_runtime.h>
#include <cuda_fp16.h>
#include <math_constants.h>
#include <cstdint>

#define C_DIM 128
#define D_DEG 64
#define NODE_NUM 8192
#define N_TOTAL 200000
#define NEG_SLOPE 0.2f
#define GRID_CTAS 296        // 2 persistent CTAs per SM
#define GROUPS 4             // independent 128-thread groups per CTA
#define GSTREAMS (GRID_CTAS * GROUPS)   // 1184 node streams

// smem layout (dynamic)
#define OFF_STAGE 0                 // [4][64][128] fp16 = 64KB (warp-private rows)
#define OFF_PARTA 65536             // [4][4][16] uint4 fp16 colmax partials = 4KB
#define OFF_PARTP 69632             // [4][4][128] f32 pool partials = 8KB
#define OFF_SRAW  77824             // [4][64] f32 = 1KB
#define OFF_SARR  78848             // [4][64] f32 = 1KB
#define OFF_WRED  79872             // [4][4] f32
#define SMEM_BYTES 79936

// Fused fp16 table: S[n][c] = fp16(feat[n][c] + mem[n][c]); 51.2MB static scratch.
__device__ __half2 g_S[(size_t)N_TOTAL * (C_DIM / 2)];
// Folded weights: v = W_max @ W_score[:128]; c0 = dot(b_max, W_score[:128]) + b_score
__device__ float g_v[C_DIM];
__device__ float g_c0;

// ---- Kernel 1: streaming fuse (feat+mem -> fp16 S, streaming reads) ----
__global__ __launch_bounds__(512)
void fuse_kernel(const float4* __restrict__ feat4,
                 const float4* __restrict__ mem4,
                 const float* __restrict__ Wmax,
                 const float* __restrict__ bmax,
                 const float* __restrict__ Wscore,
                 const float* __restrict__ bscore) {
    if (blockIdx.x == 0) {
        __shared__ float ws1[C_DIM];
        int t = threadIdx.x;
        if (t < C_DIM) ws1[t] = Wscore[t];
        __syncthreads();
        if (t < C_DIM) {
            const float* row = Wmax + t * C_DIM;
            float acc = 0.f;
#pragma unroll 8
            for (int k = 0; k < C_DIM; k++) acc += row[k] * ws1[k];
            g_v[t] = acc;
            if (t == 0) {
                float c0 = bscore[0];
                for (int k = 0; k < C_DIM; k++) c0 += bmax[k] * ws1[k];
                g_c0 = c0;
            }
        }
    }
    // exactly one uint4 store per thread: grid 6250 x 512 == 3.2M
    const int i = blockIdx.x * blockDim.x + threadIdx.x;
    // streaming (evict-first) reads keep the S output resident in L2
    float4 a0 = __ldcs(feat4 + 2 * i);
    float4 b0 = __ldcs(mem4 + 2 * i);
    float4 a1 = __ldcs(feat4 + 2 * i + 1);
    float4 b1 = __ldcs(mem4 + 2 * i + 1);
    __half2 h0 = __floats2half2_rn(a0.x + b0.x, a0.y + b0.y);
    __half2 h1 = __floats2half2_rn(a0.z + b0.z, a0.w + b0.w);
    __half2 h2 = __floats2half2_rn(a1.x + b1.x, a1.y + b1.y);
    __half2 h3 = __floats2half2_rn(a1.z + b1.z, a1.w + b1.w);
    uint4 pack;
    pack.x = *reinterpret_cast<unsigned int*>(&h0);
    pack.y = *reinterpret_cast<unsigned int*>(&h1);
    pack.z = *reinterpret_cast<unsigned int*>(&h2);
    pack.w = *reinterpret_cast<unsigned int*>(&h3);
    reinterpret_cast<uint4*>(g_S)[i] = pack;
}

__device__ __forceinline__ void cp16(unsigned int dst, const void* src) {
    asm volatile("cp.async.cg.shared.global [%0], [%1], 16;\n"
                 :: "r"(dst), "l"(src) : "memory");
}
__device__ __forceinline__ void gbar(int id) {
    asm volatile("bar.sync %0, 128;" :: "r"(id) : "memory");
}
__device__ __forceinline__ __half2 u2h(unsigned int u) {
    return *reinterpret_cast<__half2*>(&u);
}
__device__ __forceinline__ __half2 hshflx16(__half2 v) {
    unsigned int u = __shfl_xor_sync(0xffffffffu, *reinterpret_cast<unsigned int*>(&v), 16);
    return u2h(u);
}

// ---- Kernel 2: 4 warpgroup pipelines; LDS.128 two-row layout ----
__global__ __launch_bounds__(512, 2)
void community_kernel(const float* __restrict__ Wscore,
                      const float* __restrict__ Wfit,
                      const float* __restrict__ bfit,
                      float* __restrict__ out_cluster,   // [NODE_NUM, C]
                      float* __restrict__ out_scores,    // [NODE_NUM, D]
                      float* __restrict__ out_fit,       // [NODE_NUM]
                      const int* __restrict__ neighbors)
{
    extern __shared__ char smem[];

    const int t    = threadIdx.x;
    const int lane = t & 31;
    const int wid  = t >> 5;     // 0..15
    const int g    = wid >> 2;   // group 0..3
    const int gw   = wid & 3;    // warp within group
    const int tg   = t & 127;    // thread within group
    const int barid = g + 1;
    const int rsel = lane >> 4;  // which row of the pair this lane reads
    const int q16  = lane & 15;  // 16B-quad within the row (channels 8q..8q+7)

    char*  stg_b = smem + OFF_STAGE + g * 16384;                // group stage, bytes
    uint4* partA = (uint4*)(smem + OFF_PARTA) + g * 64;         // [4][16] fp16 colmax
    float* partP = (float*)(smem + OFF_PARTP) + g * 512;        // pool partials
    float* srawg = (float*)(smem + OFF_SRAW) + g * 64;
    float* sarrg = (float*)(smem + OFF_SARR) + g * 64;
    float* wredg = (float*)(smem + OFF_WRED) + g * 4;
    const unsigned int stg_u = (unsigned int)__cvta_generic_to_shared(stg_b);
    const char* Sbase = (const char*)g_S;

    // loop-invariant weights: this lane's 8 channels of W_score second half
    const float4 w2a = *reinterpret_cast<const float4*>(Wscore + C_DIM + 8 * q16);
    const float4 w2b = *reinterpret_cast<const float4*>(Wscore + C_DIM + 8 * q16 + 4);
    const float  wfitv = Wfit[tg];
    const float  bfitv = bfit[0];
    const float  c0    = g_c0;
    const __half2 NEGINF2 = __halves2half2(__ushort_as_half(0xFC00u),
                                           __ushort_as_half(0xFC00u));

    int node = blockIdx.x * GROUPS + g;
    int prev = -1;

    // ---- prologue: warp stages its OWN 16 rows (ids: 1 LDG + shfl) ----
    {
        int myid = 0;
        if (lane < 16) myid = neighbors[node * D_DEG + gw * 16 + lane];
#pragma unroll
        for (int i = 0; i < 8; i++) {
            int c  = lane + 32 * i;          // chunk within warp's 16 rows
            int r  = c >> 4, ch = c & 15;
            long long nid = __shfl_sync(0xffffffffu, myid, r);
            int row = gw * 16 + r;
            cp16(stg_u + (unsigned)(row * 256 + ch * 16), Sbase + nid * 256 + ch * 16);
        }
        asm volatile("cp.async.commit_group;\n" ::: "memory");
    }

    while (true) {
        const int  next     = node + GSTREAMS;
        const bool has_next = (next < NODE_NUM);

        asm volatile("cp.async.wait_group 0;\n" ::: "memory");
        // stage is warp-private: no barrier needed before reading it.

        // ---- Phase A: row-pair LDS.128; half-warp dot butterfly; fp16 colmax ----
        __half2 cm0 = NEGINF2, cm1 = NEGINF2, cm2 = NEGINF2, cm3 = NEGINF2;
#pragma unroll
        for (int k = 0; k < 8; k++) {
            int rr = gw * 16 + 2 * k + rsel;
            uint4 u = *reinterpret_cast<const uint4*>(stg_b + rr * 256 + q16 * 16);
            __half2 h0 = u2h(u.x), h1 = u2h(u.y), h2 = u2h(u.z), h3 = u2h(u.w);
            cm0 = __hmax2(cm0, h0); cm1 = __hmax2(cm1, h1);
            cm2 = __hmax2(cm2, h2); cm3 = __hmax2(cm3, h3);
            float2 f0 = __half22float2(h0), f1 = __half22float2(h1);
            float2 f2 = __half22float2(h2), f3 = __half22float2(h3);
            float p = f0.x * w2a.x + f0.y * w2a.y + f1.x * w2a.z + f1.y * w2a.w
                    + f2.x * w2b.x + f2.y * w2b.y + f3.x * w2b.z + f3.y * w2b.w;
            // 4-stage butterfly within each 16-lane half (row-local)
            p += __shfl_xor_sync(0xffffffffu, p, 1);
            p += __shfl_xor_sync(0xffffffffu, p, 2);
            p += __shfl_xor_sync(0xffffffffu, p, 4);
            p += __shfl_xor_sync(0xffffffffu, p, 8);
            if (q16 == 0) srawg[rr] = p;   // lane0 -> even row, lane16 -> odd row
        }
        // combine even/odd-row maxima across half-warps
        cm0 = __hmax2(cm0, hshflx16(cm0));
        cm1 = __hmax2(cm1, hshflx16(cm1));
        cm2 = __hmax2(cm2, hshflx16(cm2));
        cm3 = __hmax2(cm3, hshflx16(cm3));
        if (lane < 16) {
            partA[gw * 16 + q16] = make_uint4(*reinterpret_cast<unsigned int*>(&cm0),
                                              *reinterpret_cast<unsigned int*>(&cm1),
                                              *reinterpret_cast<unsigned int*>(&cm2),
                                              *reinterpret_cast<unsigned int*>(&cm3));
        }
        gbar(barid);   // B2: partA + sraw visible (also orders prev iter's wred writes)

        // ---- deferred fitness for previous node (ordered by B2) ----
        if (prev >= 0 && tg == 0) {
            float s = wredg[0] + wredg[1] + wredg[2] + wredg[3] + bfitv;
            out_fit[prev] = 1.f / (1.f + __expf(-s));
        }

        // ---- warp 0 only: colmax combine -> s_const -> softmax -> sarr ----
        if (gw == 0) {
            uint4 m0 = partA[q16], m1 = partA[16 + q16];
            uint4 m2 = partA[32 + q16], m3 = partA[48 + q16];
            __half2 x0 = __hmax2(__hmax2(u2h(m0.x), u2h(m1.x)), __hmax2(u2h(m2.x), u2h(m3.x)));
            __half2 x1 = __hmax2(__hmax2(u2h(m0.y), u2h(m1.y)), __hmax2(u2h(m2.y), u2h(m3.y)));
            __half2 x2 = __hmax2(__hmax2(u2h(m0.z), u2h(m1.z)), __hmax2(u2h(m2.z), u2h(m3.z)));
            __half2 x3 = __hmax2(__hmax2(u2h(m0.w), u2h(m1.w)), __hmax2(u2h(m2.w), u2h(m3.w)));
            float p = 0.f;
            if (lane < 16) {
                const float4* gvp = reinterpret_cast<const float4*>(g_v + 8 * q16);
                float4 ga = __ldg(gvp), gb = __ldg(gvp + 1);
                float2 c0v = __half22float2(x0), c1v = __half22float2(x1);
                float2 c2v = __half22float2(x2), c3v = __half22float2(x3);
                p = c0v.x * ga.x + c0v.y * ga.y + c1v.x * ga.z + c1v.y * ga.w
                  + c2v.x * gb.x + c2v.y * gb.y + c3v.x * gb.z + c3v.y * gb.w;
            }
#pragma unroll
            for (int o = 16; o > 0; o >>= 1) p += __shfl_xor_sync(0xffffffffu, p, o);
            const float s_const = p + c0;

            float a0 = s_const + srawg[lane];
            float a1 = s_const + srawg[lane + 32];
            a0 = (a0 >= 0.f) ? a0 : NEG_SLOPE * a0;
            a1 = (a1 >= 0.f) ? a1 : NEG_SLOPE * a1;
            float mx = fmaxf(a0, a1);
#pragma unroll
            for (int o = 16; o > 0; o >>= 1) mx = fmaxf(mx, __shfl_xor_sync(0xffffffffu, mx, o));
            float e0 = __expf(a0 - mx), e1 = __expf(a1 - mx);
            float sm = e0 + e1;
#pragma unroll
            for (int o = 16; o > 0; o >>= 1) sm += __shfl_xor_sync(0xffffffffu, sm, o);
            float inv = 1.f / sm;
            float s0 = e0 * inv, s1 = e1 * inv;
            sarrg[lane]      = s0;
            sarrg[lane + 32] = s1;
            out_scores[node * D_DEG + lane]      = s0;
            out_scores[node * D_DEG + lane + 32] = s1;
        }
        gbar(barid);   // B3: sarr ready

        // ---- next-node ids (consumed by D's interleaved prefetch) ----
        int myid2 = 0;
        if (has_next && lane < 16) myid2 = neighbors[next * D_DEG + gw * 16 + lane];

        // ---- Phase D: pooling over row pairs; prefetch pair k each iteration ----
        {
            float a0 = 0.f, a1 = 0.f, a2 = 0.f, a3 = 0.f;
            float a4 = 0.f, a5 = 0.f, a6 = 0.f, a7 = 0.f;
#pragma unroll
            for (int k = 0; k < 8; k++) {
                int rr = gw * 16 + 2 * k + rsel;
                float sc = sarrg[rr];
                uint4 u = *reinterpret_cast<const uint4*>(stg_b + rr * 256 + q16 * 16);
                float2 f0 = __half22float2(u2h(u.x)), f1 = __half22float2(u2h(u.y));
                float2 f2 = __half22float2(u2h(u.z)), f3 = __half22float2(u2h(u.w));
                a0 = fmaf(sc, f0.x, a0); a1 = fmaf(sc, f0.y, a1);
                a2 = fmaf(sc, f1.x, a2); a3 = fmaf(sc, f1.y, a3);
                a4 = fmaf(sc, f2.x, a4); a5 = fmaf(sc, f2.y, a5);
                a6 = fmaf(sc, f3.x, a6); a7 = fmaf(sc, f3.y, a7);
                // refill consumed pair k with next node's rows
                if (has_next) {
                    int c  = k * 32 + lane;          // chunk id
                    int rpf = c >> 4, ch = c & 15;   // rpf in {2k, 2k+1}
                    long long nid = __shfl_sync(0xffffffffu, myid2, rpf);
                    int wrow = gw * 16 + rpf;
                    cp16(stg_u + (unsigned)(wrow * 256 + ch * 16),
                         Sbase + nid * 256 + ch * 16);
                }
            }
            if (has_next) asm volatile("cp.async.commit_group;\n" ::: "memory");
            // combine even/odd-row partial pools across half-warps
            a0 += __shfl_xor_sync(0xffffffffu, a0, 16);
            a1 += __shfl_xor_sync(0xffffffffu, a1, 16);
            a2 += __shfl_xor_sync(0xffffffffu, a2, 16);
            a3 += __shfl_xor_sync(0xffffffffu, a3, 16);
            a4 += __shfl_xor_sync(0xffffffffu, a4, 16);
            a5 += __shfl_xor_sync(0xffffffffu, a5, 16);
            a6 += __shfl_xor_sync(0xffffffffu, a6, 16);
            a7 += __shfl_xor_sync(0xffffffffu, a7, 16);
            if (lane < 16) {
                float4* dst = reinterpret_cast<float4*>(partP + gw * 128 + q16 * 8);
                dst[0] = make_float4(a0, a1, a2, a3);
                dst[1] = make_float4(a4, a5, a6, a7);
            }
        }
        gbar(barid);   // B4: partP visible

        // ---- Phase E: cluster sum + output + fitness partials ----
        {
            float cf = partP[tg] + partP[128 + tg] + partP[256 + tg] + partP[384 + tg];
            out_cluster[node * C_DIM + tg] = cf;
            float p = cf * wfitv;
#pragma unroll
            for (int o = 16; o > 0; o >>= 1) p += __shfl_xor_sync(0xffffffffu, p, o);
            if (lane == 0) wredg[gw] = p;   // consumed after next iter's B2 (or tail)
        }

        prev = node;
        if (!has_next) break;
        node = next;
    }

    // ---- tail: final node's fitness ----
    gbar(barid);
    if (tg == 0) {
        float s = wredg[0] + wredg[1] + wredg[2] + wredg[3] + bfitv;
        out_fit[prev] = 1.f / (1.f + __expf(-s));
    }
}

extern "C" void kernel_launch(void* const* d_in, const int* in_sizes, int n_in,
                              void* d_out, int out_size) {
    const float* feat   = (const float*)d_in[0];
    const float* mem    = (const float*)d_in[1];
    const float* Wmax   = (const float*)d_in[2];
    const float* bmax   = (const float*)d_in[3];
    const float* Wscore = (const float*)d_in[4];
    const float* bscore = (const float*)d_in[5];
    const float* Wfit   = (const float*)d_in[6];
    const float* bfit   = (const float*)d_in[7];
    const int*   nbrs   = (const int*)d_in[8];

    float* out = (float*)d_out;
    float* out_cluster = out;                                        // 8192*128
    float* out_scores  = out + NODE_NUM * C_DIM;                     // 8192*64
    float* out_fit     = out + NODE_NUM * C_DIM + NODE_NUM * D_DEG;  // 8192

    cudaFuncSetAttribute(community_kernel,
                         cudaFuncAttributeMaxDynamicSharedMemorySize, SMEM_BYTES);

    // 6250 x 512 threads == 3.2M == exactly one 16B S-store per thread
    fuse_kernel<<<6250, 512>>>((const float4*)feat, (const float4*)mem,
                               Wmax, bmax, Wscore, bscore);
    community_kernel<<<GRID_CTAS, 512, SMEM_BYTES>>>(Wscore, Wfit, bfit,
                                                     out_cluster, out_scores, out_fit, nbrs);
}

// round 13
// speedup vs baseline: 1.6018x; 1.0640x over previous
#include <cuda_runtime.h>
#include <cuda_fp16.h>
#include <math_constants.h>
#include <cstdint>

#define C_DIM 128
#define D_DEG 64
#define NODE_NUM 8192
#define N_TOTAL 200000
#define NEG_SLOPE 0.2f
#define GRID_CTAS 296        // 2 persistent CTAs per SM
#define GROUPS 4             // independent 128-thread groups per CTA
#define GSTREAMS (GRID_CTAS * GROUPS)   // 1184 node streams

// smem layout (dynamic)
#define OFF_STAGE 0                 // [4][64][128] fp16 = 64KB (warp-private rows)
#define OFF_PARTA 65536             // [4][4][32] uint2 fp16 colmax partials = 4KB
#define OFF_PARTP 69632             // [4][4][128] f32 pool partials = 8KB
#define OFF_SRAW  77824             // [4][64] f32 = 1KB
#define OFF_SARR  78848             // [4][64] f32 = 1KB
#define OFF_WRED  79872             // [4][4] f32
#define SMEM_BYTES 79936

// Fused fp16 table: S[n][c] = fp16(feat[n][c] + mem[n][c]); 51.2MB static scratch.
__device__ __half2 g_S[(size_t)N_TOTAL * (C_DIM / 2)];
// Folded weights: v = W_max @ W_score[:128]; c0 = dot(b_max, W_score[:128]) + b_score
__device__ float g_v[C_DIM];
__device__ float g_c0;

// ---- Kernel 1 (R12-proven): streaming fuse, one uint4 store per thread ----
__global__ __launch_bounds__(512)
void fuse_kernel(const float4* __restrict__ feat4,
                 const float4* __restrict__ mem4,
                 const float* __restrict__ Wmax,
                 const float* __restrict__ bmax,
                 const float* __restrict__ Wscore,
                 const float* __restrict__ bscore) {
    if (blockIdx.x == 0) {
        __shared__ float ws1[C_DIM];
        int t = threadIdx.x;
        if (t < C_DIM) ws1[t] = Wscore[t];
        __syncthreads();
        if (t < C_DIM) {
            const float* row = Wmax + t * C_DIM;
            float acc = 0.f;
#pragma unroll 8
            for (int k = 0; k < C_DIM; k++) acc += row[k] * ws1[k];
            g_v[t] = acc;
            if (t == 0) {
                float c0 = bscore[0];
                for (int k = 0; k < C_DIM; k++) c0 += bmax[k] * ws1[k];
                g_c0 = c0;
            }
        }
    }
    // exactly one uint4 store per thread: grid 6250 x 512 == 3.2M
    const int i = blockIdx.x * blockDim.x + threadIdx.x;
    // streaming (evict-first) reads keep the S output resident in L2
    float4 a0 = __ldcs(feat4 + 2 * i);
    float4 b0 = __ldcs(mem4 + 2 * i);
    float4 a1 = __ldcs(feat4 + 2 * i + 1);
    float4 b1 = __ldcs(mem4 + 2 * i + 1);
    __half2 h0 = __floats2half2_rn(a0.x + b0.x, a0.y + b0.y);
    __half2 h1 = __floats2half2_rn(a0.z + b0.z, a0.w + b0.w);
    __half2 h2 = __floats2half2_rn(a1.x + b1.x, a1.y + b1.y);
    __half2 h3 = __floats2half2_rn(a1.z + b1.z, a1.w + b1.w);
    uint4 pack;
    pack.x = *reinterpret_cast<unsigned int*>(&h0);
    pack.y = *reinterpret_cast<unsigned int*>(&h1);
    pack.z = *reinterpret_cast<unsigned int*>(&h2);
    pack.w = *reinterpret_cast<unsigned int*>(&h3);
    reinterpret_cast<uint4*>(g_S)[i] = pack;
}

__device__ __forceinline__ void cp16(unsigned int dst, const void* src) {
    asm volatile("cp.async.cg.shared.global [%0], [%1], 16;\n"
                 :: "r"(dst), "l"(src) : "memory");
}
__device__ __forceinline__ void gbar(int id) {
    asm volatile("bar.sync %0, 128;" :: "r"(id) : "memory");
}
__device__ __forceinline__ __half2 u2h(unsigned int u) {
    return *reinterpret_cast<__half2*>(&u);
}

// ---- Kernel 2 (R11-proven): 4 warpgroup pipelines; quad reductions;
//      single-warp softmax; prefetch interleaved into pooling ----
__global__ __launch_bounds__(512, 2)
void community_kernel(const float* __restrict__ Wscore,
                      const float* __restrict__ Wfit,
                      const float* __restrict__ bfit,
                      float* __restrict__ out_cluster,   // [NODE_NUM, C]
                      float* __restrict__ out_scores,    // [NODE_NUM, D]
                      float* __restrict__ out_fit,       // [NODE_NUM]
                      const int* __restrict__ neighbors)
{
    extern __shared__ char smem[];

    const int t    = threadIdx.x;
    const int lane = t & 31;
    const int wid  = t >> 5;     // 0..15
    const int g    = wid >> 2;   // group 0..3
    const int gw   = wid & 3;    // warp within group
    const int tg   = t & 127;    // thread within group
    const int barid = g + 1;

    char*  stg_b = smem + OFF_STAGE + g * 16384;                // group stage, bytes
    __half2* stg = (__half2*)stg_b;                             // [64][64] half2
    uint2* partA = (uint2*)(smem + OFF_PARTA) + g * 128;        // [4][32] fp16 colmax
    float* partP = (float*)(smem + OFF_PARTP) + g * 512;        // pool partials
    float* srawg = (float*)(smem + OFF_SRAW) + g * 64;
    float* sarrg = (float*)(smem + OFF_SARR) + g * 64;
    float* wredg = (float*)(smem + OFF_WRED) + g * 4;
    const unsigned int stg_u = (unsigned int)__cvta_generic_to_shared(stg_b);
    const char* Sbase = (const char*)g_S;

    // loop-invariant weights
    const float4 w2v   = *reinterpret_cast<const float4*>(Wscore + C_DIM + 4 * lane);
    const float4 gv4   = *reinterpret_cast<const float4*>(g_v + 4 * lane);
    const float  wfitv = Wfit[tg];
    const float  bfitv = bfit[0];
    const float  c0    = g_c0;
    const __half2 NEGINF2 = __halves2half2(__ushort_as_half(0xFC00u),
                                           __ushort_as_half(0xFC00u));

    int node = blockIdx.x * GROUPS + g;
    int prev = -1;

    // ---- prologue: warp stages its OWN 16 rows (ids: 1 LDG + shfl) ----
    {
        int myid = 0;
        if (lane < 16) myid = neighbors[node * D_DEG + gw * 16 + lane];
#pragma unroll
        for (int i = 0; i < 8; i++) {
            int c  = lane + 32 * i;          // chunk within warp's 16 rows
            int r  = c >> 4, ch = c & 15;
            long long nid = __shfl_sync(0xffffffffu, myid, r);
            int row = gw * 16 + r;
            cp16(stg_u + (unsigned)(row * 256 + ch * 16), Sbase + nid * 256 + ch * 16);
        }
        asm volatile("cp.async.commit_group;\n" ::: "memory");
    }

    while (true) {
        const int  next     = node + GSTREAMS;
        const bool has_next = (next < NODE_NUM);

        asm volatile("cp.async.wait_group 0;\n" ::: "memory");
        // stage is warp-private: no barrier needed before reading it.

        // ---- Phase A: quad row-dot reduction + fp16 colmax over own 16 rows ----
        __half2 cmx0 = NEGINF2, cmx1 = NEGINF2;
#pragma unroll
        for (int k = 0; k < 4; k++) {
            int r0 = gw * 16 + 4 * k;
            uint2 u0 = *reinterpret_cast<const uint2*>(stg + (r0 + 0) * 64 + lane * 2);
            uint2 u1 = *reinterpret_cast<const uint2*>(stg + (r0 + 1) * 64 + lane * 2);
            uint2 u2 = *reinterpret_cast<const uint2*>(stg + (r0 + 2) * 64 + lane * 2);
            uint2 u3 = *reinterpret_cast<const uint2*>(stg + (r0 + 3) * 64 + lane * 2);
            __half2 a0x = u2h(u0.x), a0y = u2h(u0.y);
            __half2 a1x = u2h(u1.x), a1y = u2h(u1.y);
            __half2 a2x = u2h(u2.x), a2y = u2h(u2.y);
            __half2 a3x = u2h(u3.x), a3y = u2h(u3.y);
            cmx0 = __hmax2(cmx0, __hmax2(__hmax2(a0x, a1x), __hmax2(a2x, a3x)));
            cmx1 = __hmax2(cmx1, __hmax2(__hmax2(a0y, a1y), __hmax2(a2y, a3y)));
            float2 f0x = __half22float2(a0x), f0y = __half22float2(a0y);
            float2 f1x = __half22float2(a1x), f1y = __half22float2(a1y);
            float2 f2x = __half22float2(a2x), f2y = __half22float2(a2y);
            float2 f3x = __half22float2(a3x), f3y = __half22float2(a3y);
            float p0 = f0x.x * w2v.x + f0x.y * w2v.y + f0y.x * w2v.z + f0y.y * w2v.w;
            float p1 = f1x.x * w2v.x + f1x.y * w2v.y + f1y.x * w2v.z + f1y.y * w2v.w;
            float p2 = f2x.x * w2v.x + f2x.y * w2v.y + f2y.x * w2v.z + f2y.y * w2v.w;
            float p3 = f3x.x * w2v.x + f3x.y * w2v.y + f3y.x * w2v.z + f3y.y * w2v.w;
            // quad butterfly: lane%4 == m ends with row r0+m's full dot
            float tA = (lane & 1) ? p0 : p1;
            tA = __shfl_xor_sync(0xffffffffu, tA, 1);
            float v01 = ((lane & 1) ? p1 : p0) + tA;
            float tB = (lane & 1) ? p2 : p3;
            tB = __shfl_xor_sync(0xffffffffu, tB, 1);
            float v23 = ((lane & 1) ? p3 : p2) + tB;
            float tC = (lane & 2) ? v01 : v23;
            tC = __shfl_xor_sync(0xffffffffu, tC, 2);
            float v = ((lane & 2) ? v23 : v01) + tC;
            v += __shfl_xor_sync(0xffffffffu, v, 4);
            v += __shfl_xor_sync(0xffffffffu, v, 8);
            v += __shfl_xor_sync(0xffffffffu, v, 16);
            if (lane < 4) srawg[r0 + lane] = v;
        }
        partA[gw * 32 + lane] = make_uint2(*reinterpret_cast<unsigned int*>(&cmx0),
                                           *reinterpret_cast<unsigned int*>(&cmx1));
        gbar(barid);   // B2: partA + sraw visible (also orders prev iter's wred writes)

        // ---- deferred fitness for previous node (ordered by B2) ----
        if (prev >= 0 && tg == 0) {
            float s = wredg[0] + wredg[1] + wredg[2] + wredg[3] + bfitv;
            out_fit[prev] = 1.f / (1.f + __expf(-s));
        }

        // ---- warp 0 only: colmax combine -> s_const -> softmax -> sarr ----
        if (gw == 0) {
            uint2 m0 = partA[0   + lane], m1 = partA[32  + lane];
            uint2 m2 = partA[64  + lane], m3 = partA[96  + lane];
            __half2 x0 = __hmax2(__hmax2(u2h(m0.x), u2h(m1.x)),
                                 __hmax2(u2h(m2.x), u2h(m3.x)));
            __half2 x1 = __hmax2(__hmax2(u2h(m0.y), u2h(m1.y)),
                                 __hmax2(u2h(m2.y), u2h(m3.y)));
            float2 c01 = __half22float2(x0);
            float2 c23 = __half22float2(x1);
            float p = c01.x * gv4.x + c01.y * gv4.y + c23.x * gv4.z + c23.y * gv4.w;
#pragma unroll
            for (int o = 16; o > 0; o >>= 1) p += __shfl_xor_sync(0xffffffffu, p, o);
            const float s_const = p + c0;

            float a0 = s_const + srawg[lane];
            float a1 = s_const + srawg[lane + 32];
            a0 = (a0 >= 0.f) ? a0 : NEG_SLOPE * a0;
            a1 = (a1 >= 0.f) ? a1 : NEG_SLOPE * a1;
            float mx = fmaxf(a0, a1);
#pragma unroll
            for (int o = 16; o > 0; o >>= 1) mx = fmaxf(mx, __shfl_xor_sync(0xffffffffu, mx, o));
            float e0 = __expf(a0 - mx), e1 = __expf(a1 - mx);
            float sm = e0 + e1;
#pragma unroll
            for (int o = 16; o > 0; o >>= 1) sm += __shfl_xor_sync(0xffffffffu, sm, o);
            float inv = 1.f / sm;
            float s0 = e0 * inv, s1 = e1 * inv;
            sarrg[lane]      = s0;
            sarrg[lane + 32] = s1;
            out_scores[node * D_DEG + lane]      = s0;
            out_scores[node * D_DEG + lane + 32] = s1;
        }
        gbar(barid);   // B3: sarr ready

        // ---- next-node ids (loaded early, consumed in D's interleaved prefetch) ----
        int myid2 = 0;
        if (has_next && lane < 16) myid2 = neighbors[next * D_DEG + gw * 16 + lane];

        // ---- Phase D: weighted pooling; prefetch interleaved every 2 rows ----
        {
            float a0 = 0.f, a1 = 0.f, a2 = 0.f, a3 = 0.f;
#pragma unroll
            for (int r = 0; r < 16; r++) {
                int row = gw * 16 + r;
                float sc = sarrg[row];   // LDS broadcast
                uint2 u = *reinterpret_cast<const uint2*>(stg + row * 64 + lane * 2);
                float2 f0 = __half22float2(u2h(u.x));
                float2 f1 = __half22float2(u2h(u.y));
                a0 = fmaf(sc, f0.x, a0); a1 = fmaf(sc, f0.y, a1);
                a2 = fmaf(sc, f1.x, a2); a3 = fmaf(sc, f1.y, a3);
                // after the odd row of each pair is consumed, refill that pair
                if ((r & 1) && has_next) {
                    int pair = r >> 1;                  // 0..7
                    int c  = pair * 32 + lane;          // chunk id 0..255
                    int rr = c >> 4, ch = c & 15;       // rr in {2*pair, 2*pair+1} <= r
                    long long nid = __shfl_sync(0xffffffffu, myid2, rr);
                    int wrow = gw * 16 + rr;
                    cp16(stg_u + (unsigned)(wrow * 256 + ch * 16),
                         Sbase + nid * 256 + ch * 16);
                }
            }
            if (has_next) asm volatile("cp.async.commit_group;\n" ::: "memory");
            *reinterpret_cast<float4*>(partP + gw * 128 + lane * 4) = make_float4(a0, a1, a2, a3);
        }
        gbar(barid);   // B4: partP visible

        // ---- Phase E: cluster sum + output + fitness partials ----
        {
            float cf = partP[tg] + partP[128 + tg] + partP[256 + tg] + partP[384 + tg];
            out_cluster[node * C_DIM + tg] = cf;
            float p = cf * wfitv;
#pragma unroll
            for (int o = 16; o > 0; o >>= 1) p += __shfl_xor_sync(0xffffffffu, p, o);
            if (lane == 0) wredg[gw] = p;   // consumed after next iter's B2 (or tail)
        }

        prev = node;
        if (!has_next) break;
        node = next;
    }

    // ---- tail: final node's fitness ----
    gbar(barid);
    if (tg == 0) {
        float s = wredg[0] + wredg[1] + wredg[2] + wredg[3] + bfitv;
        out_fit[prev] = 1.f / (1.f + __expf(-s));
    }
}

extern "C" void kernel_launch(void* const* d_in, const int* in_sizes, int n_in,
                              void* d_out, int out_size) {
    const float* feat   = (const float*)d_in[0];
    const float* mem    = (const float*)d_in[1];
    const float* Wmax   = (const float*)d_in[2];
    const float* bmax   = (const float*)d_in[3];
    const float* Wscore = (const float*)d_in[4];
    const float* bscore = (const float*)d_in[5];
    const float* Wfit   = (const float*)d_in[6];
    const float* bfit   = (const float*)d_in[7];
    const int*   nbrs   = (const int*)d_in[8];

    float* out = (float*)d_out;
    float* out_cluster = out;                                        // 8192*128
    float* out_scores  = out + NODE_NUM * C_DIM;                     // 8192*64
    float* out_fit     = out + NODE_NUM * C_DIM + NODE_NUM * D_DEG;  // 8192

    cudaFuncSetAttribute(community_kernel,
                         cudaFuncAttributeMaxDynamicSharedMemorySize, SMEM_BYTES);

    // 6250 x 512 threads == 3.2M == exactly one 16B S-store per thread
    fuse_kernel<<<6250, 512>>>((const float4*)feat, (const float4*)mem,
                               Wmax, bmax, Wscore, bscore);
    community_kernel<<<GRID_CTAS, 512, SMEM_BYTES>>>(Wscore, Wfit, bfit,
                                                     out_cluster, out_scores, out_fit, nbrs);
}